// round 12
// baseline (speedup 1.0000x reference)
#include <cuda_runtime.h>
#include <cuda_bf16.h>
#include <math.h>
#include <cstdint>

#define NB 4
#define NT 2048
#define NC 1024
#define NH 16
#define HD 64
#define MM (NB*NT)          // 8192

// ---------------- global scratch (device globals; no runtime alloc) --------
__device__ __nv_bfloat16 g_xh[(size_t)MM*NC],    g_xl[(size_t)MM*NC];
__device__ __nv_bfloat16 g_wah[(size_t)3*NC*NC], g_wal[(size_t)3*NC*NC];
__device__ __nv_bfloat16 g_wph[(size_t)NC*NC],   g_wpl[(size_t)NC*NC];
__device__ __nv_bfloat16 g_qkvh[(size_t)MM*3*NC],g_qkvl[(size_t)MM*3*NC];
__device__ __nv_bfloat16 g_atth[(size_t)MM*NC],  g_attl[(size_t)MM*NC];

// ---------------- helpers --------------------------------------------------
__device__ __forceinline__ uint32_t s2u(const void* p) {
    return (uint32_t)__cvta_generic_to_shared(p);
}
__device__ __forceinline__ void cp16(uint32_t dst, const void* src) {
    asm volatile("cp.async.cg.shared.global [%0], [%1], 16;" :: "r"(dst), "l"(src));
}
__device__ __forceinline__ void cp_commit() {
    asm volatile("cp.async.commit_group;" ::: "memory");
}
__device__ __forceinline__ void cp_wait1() {
    asm volatile("cp.async.wait_group 1;" ::: "memory");
}
__device__ __forceinline__ void cp_wait0() {
    asm volatile("cp.async.wait_group 0;" ::: "memory");
}
__device__ __forceinline__ void ldm4(uint32_t& r0, uint32_t& r1, uint32_t& r2,
                                     uint32_t& r3, uint32_t a) {
    asm volatile("ldmatrix.sync.aligned.m8n8.x4.shared.b16 {%0,%1,%2,%3}, [%4];"
                 : "=r"(r0), "=r"(r1), "=r"(r2), "=r"(r3) : "r"(a));
}
__device__ __forceinline__ void ldm4t(uint32_t& r0, uint32_t& r1, uint32_t& r2,
                                      uint32_t& r3, uint32_t a) {
    asm volatile("ldmatrix.sync.aligned.m8n8.x4.trans.shared.b16 {%0,%1,%2,%3}, [%4];"
                 : "=r"(r0), "=r"(r1), "=r"(r2), "=r"(r3) : "r"(a));
}
__device__ __forceinline__ void mma_bf16(float* c, uint32_t a0, uint32_t a1,
                                         uint32_t a2, uint32_t a3,
                                         uint32_t b0, uint32_t b1) {
    asm volatile("mma.sync.aligned.m16n8k16.row.col.f32.bf16.bf16.f32 "
                 "{%0,%1,%2,%3}, {%4,%5,%6,%7}, {%8,%9}, {%0,%1,%2,%3};"
                 : "+f"(c[0]), "+f"(c[1]), "+f"(c[2]), "+f"(c[3])
                 : "r"(a0), "r"(a1), "r"(a2), "r"(a3), "r"(b0), "r"(b1));
}

// Split fp32 -> bf16 hi + bf16 lo, packed pair stores
__device__ __forceinline__ void split_store2(float x, float y,
                                             __nv_bfloat16* hp, __nv_bfloat16* lp)
{
    __nv_bfloat16 hx = __float2bfloat16(x);
    __nv_bfloat16 hy = __float2bfloat16(y);
    float rx = x - __bfloat162float(hx);
    float ry = y - __bfloat162float(hy);
    *(__nv_bfloat162*)hp = __halves2bfloat162(hx, hy);
    *(__nv_bfloat162*)lp = __halves2bfloat162(__float2bfloat16(rx), __float2bfloat16(ry));
}
__device__ __forceinline__ void pack_hilo(float x, float y, uint32_t& h, uint32_t& l)
{
    __nv_bfloat16 hx = __float2bfloat16(x);
    __nv_bfloat16 hy = __float2bfloat16(y);
    float rx = x - __bfloat162float(hx);
    float ry = y - __bfloat162float(hy);
    __nv_bfloat162 hv = __halves2bfloat162(hx, hy);
    __nv_bfloat162 lv = __halves2bfloat162(__float2bfloat16(rx), __float2bfloat16(ry));
    h = *(uint32_t*)&hv;
    l = *(uint32_t*)&lv;
}

// ---------------- split kernel (f32 -> bf16 hi/lo) -------------------------
__global__ __launch_bounds__(256) void split_kernel(
    const float4* __restrict__ src, __nv_bfloat16* __restrict__ dh,
    __nv_bfloat16* __restrict__ dl, int n4)
{
    int i = blockIdx.x * 256 + threadIdx.x;
    if (i >= n4) return;
    float4 v = src[i];
    split_store2(v.x, v.y, dh + (size_t)i*4,     dl + (size_t)i*4);
    split_store2(v.z, v.w, dh + (size_t)i*4 + 2, dl + (size_t)i*4 + 2);
}

// ---------------------------------------------------------------------------
// mma.sync GEMM on pre-split bf16 (unchanged from R8): C = A * B^T, K=1024.
// CTA 128x256, 8 warps (warp = 64x64), BK=64, 2-stage, split prefetch issue.
// ---------------------------------------------------------------------------
#define GROW 144
#define GABUF (128*GROW)            // 18432
#define GBBUF (256*GROW)            // 36864
#define GSTG  (2*GABUF + 2*GBBUF)   // 110592 per stage
#define GEMM_SMEM (2*GSTG)          // 221184
#define ELD 260

__device__ __forceinline__ void g_load_A(
    uint32_t sbase, int st, int kt, int m0, int tid,
    const __nv_bfloat16* __restrict__ Ah, const __nv_bfloat16* __restrict__ Al)
{
    const int koff = kt * 64;
    const uint32_t dbase = sbase + st * GSTG;
#pragma unroll
    for (int i = 0; i < 4; i++) {
        int gidx = i * 256 + tid;
        int row = gidx >> 3, c = gidx & 7;
        uint32_t doff = row * GROW + c * 16;
        size_t soff = (size_t)(m0 + row) * 1024 + koff + c * 8;
        cp16(dbase + doff,         Ah + soff);
        cp16(dbase + GABUF + doff, Al + soff);
    }
}
__device__ __forceinline__ void g_load_B(
    uint32_t sbase, int st, int kt, int n0, int tid,
    const __nv_bfloat16* __restrict__ Bh, const __nv_bfloat16* __restrict__ Bl)
{
    const int koff = kt * 64;
    const uint32_t dbase = sbase + st * GSTG + 2*GABUF;
#pragma unroll
    for (int i = 0; i < 8; i++) {
        int gidx = i * 256 + tid;
        int row = gidx >> 3, c = gidx & 7;
        uint32_t doff = row * GROW + c * 16;
        size_t soff = (size_t)(n0 + row) * 1024 + koff + c * 8;
        cp16(dbase + doff,         Bh + soff);
        cp16(dbase + GBBUF + doff, Bl + soff);
    }
}

__global__ __launch_bounds__(256, 1) void gemm_mma_kernel(
    const __nv_bfloat16* __restrict__ Ah, const __nv_bfloat16* __restrict__ Al,
    const __nv_bfloat16* __restrict__ Bh, const __nv_bfloat16* __restrict__ Bl,
    __nv_bfloat16* __restrict__ outH, __nv_bfloat16* __restrict__ outL,
    float* __restrict__ outF, const float* __restrict__ bias,
    int ldc, int mode)
{
    extern __shared__ char sm[];
    const uint32_t sbase = s2u(sm);
    const int tid  = threadIdx.x;
    const int warp = tid >> 5;
    const int lid  = tid & 31;
    const int g    = lid >> 2;
    const int qr   = lid & 3;
    const int grp  = lid >> 3;
    const int rr   = lid & 7;

    const int m0 = blockIdx.y << 7;
    const int n0 = blockIdx.x << 8;
    const int mw = (warp >> 2) * 64;
    const int nw = (warp & 3) * 64;

    const uint32_t a_rowsel = ((grp & 1) ? 8 : 0) + rr;
    const uint32_t a_colsel = (grp >= 2) ? 16 : 0;
    const uint32_t b_rowsel = ((grp >= 2) ? 8 : 0) + rr;
    const uint32_t b_colsel = (grp & 1) ? 16 : 0;

    float acc[4][8][4];
#pragma unroll
    for (int mt = 0; mt < 4; mt++)
#pragma unroll
        for (int nt = 0; nt < 8; nt++) {
            acc[mt][nt][0] = 0.f; acc[mt][nt][1] = 0.f;
            acc[mt][nt][2] = 0.f; acc[mt][nt][3] = 0.f;
        }

    g_load_A(sbase, 0, 0, m0, tid, Ah, Al);
    g_load_B(sbase, 0, 0, n0, tid, Bh, Bl);
    cp_commit();

    int stidx = 0;
    for (int kt = 0; kt < 16; kt++) {
        cp_wait0();
        __syncthreads();

        const uint32_t sb  = sbase + stidx * GSTG;
        const uint32_t sAh = sb;
        const uint32_t sAl = sb + GABUF;
        const uint32_t sBh = sb + 2*GABUF;
        const uint32_t sBl = sb + 2*GABUF + GBBUF;

        if (kt + 1 < 16)
            g_load_A(sbase, stidx ^ 1, kt + 1, m0, tid, Ah, Al);

#pragma unroll
        for (int half = 0; half < 2; half++) {
#pragma unroll
            for (int kq = 0; kq < 2; kq++) {
                const int kk = half*2 + kq;
                uint32_t ah[4][4], al[4][4];
#pragma unroll
                for (int mt = 0; mt < 4; mt++) {
                    uint32_t ra = (mw + mt*16 + a_rowsel) * GROW + kk*32 + a_colsel;
                    ldm4(ah[mt][0], ah[mt][1], ah[mt][2], ah[mt][3], sAh + ra);
                    ldm4(al[mt][0], al[mt][1], al[mt][2], al[mt][3], sAl + ra);
                }
#pragma unroll
                for (int nc = 0; nc < 4; nc++) {
                    uint32_t rb = (nw + nc*16 + b_rowsel) * GROW + kk*32 + b_colsel;
                    uint32_t bh0, bh1, bh2, bh3, bl0, bl1, bl2, bl3;
                    ldm4(bh0, bh1, bh2, bh3, sBh + rb);
                    ldm4(bl0, bl1, bl2, bl3, sBl + rb);
#pragma unroll
                    for (int mt = 0; mt < 4; mt++) {
                        mma_bf16(acc[mt][2*nc],   ah[mt][0], ah[mt][1], ah[mt][2], ah[mt][3], bh0, bh1);
                        mma_bf16(acc[mt][2*nc+1], ah[mt][0], ah[mt][1], ah[mt][2], ah[mt][3], bh2, bh3);
                    }
#pragma unroll
                    for (int mt = 0; mt < 4; mt++) {
                        mma_bf16(acc[mt][2*nc],   ah[mt][0], ah[mt][1], ah[mt][2], ah[mt][3], bl0, bl1);
                        mma_bf16(acc[mt][2*nc+1], ah[mt][0], ah[mt][1], ah[mt][2], ah[mt][3], bl2, bl3);
                    }
#pragma unroll
                    for (int mt = 0; mt < 4; mt++) {
                        mma_bf16(acc[mt][2*nc],   al[mt][0], al[mt][1], al[mt][2], al[mt][3], bh0, bh1);
                        mma_bf16(acc[mt][2*nc+1], al[mt][0], al[mt][1], al[mt][2], al[mt][3], bh2, bh3);
                    }
                }
            }
            if (half == 0) {
                if (kt + 1 < 16)
                    g_load_B(sbase, stidx ^ 1, kt + 1, n0, tid, Bh, Bl);
                cp_commit();
            }
        }
        stidx ^= 1;
    }

    __syncthreads();
    float* Sst = (float*)sm;
#pragma unroll
    for (int mt = 0; mt < 4; mt++) {
        int row = mw + mt*16 + g;
#pragma unroll
        for (int nt = 0; nt < 8; nt++) {
            int col = nw + nt*8 + qr*2;
            *(float2*)&Sst[row*ELD + col]       = make_float2(acc[mt][nt][0], acc[mt][nt][1]);
            *(float2*)&Sst[(row+8)*ELD + col]   = make_float2(acc[mt][nt][2], acc[mt][nt][3]);
        }
    }
    __syncthreads();

    if (mode == 0) {
#pragma unroll 1
        for (int r = 0; r < 16; r++) {
            int row = warp*16 + r;
            size_t ob = (size_t)(m0 + row) * ldc + n0;
#pragma unroll
            for (int blk = 0; blk < 4; blk++) {
                int c = blk*64 + lid*2;
                float2 v = *(float2*)&Sst[row*ELD + c];
                split_store2(v.x, v.y, outH + ob + c, outL + ob + c);
            }
        }
    } else {
#pragma unroll 1
        for (int r = 0; r < 16; r++) {
            int row = warp*16 + r;
            size_t ob = (size_t)(m0 + row) * ldc + n0;
#pragma unroll
            for (int blk = 0; blk < 2; blk++) {
                int c = blk*128 + lid*4;
                float4 v = *(float4*)&Sst[row*ELD + c];
                v.x += bias[n0 + c];     v.y += bias[n0 + c + 1];
                v.z += bias[n0 + c + 2]; v.w += bias[n0 + c + 3];
                *(float4*)(outF + ob + c) = v;
            }
        }
    }
}

// ---------------------------------------------------------------------------
// Register-resident flash attention. 128 q rows, 8 warps, kv macro-tile 128
// (2x64 subs). ANTI-PHASE scheduling: warps 0-3 process sub0 then sub1;
// warps 4-7 process sub1 then sub0. Each SMSP (warp w, w+4) thus has one
// warp in MMA while the other is in softmax -> tensor pipe stays fed.
// exp2-folded softmax, deferred l-reduction.
// ---------------------------------------------------------------------------
#define AROW 144
#define AQ_BYTES   (128*AROW)          // 18432
#define AKV_BUF    (128*AROW)          // 18432 per tensor buffer
#define AKV_STAGE  (4*AKV_BUF)         // 73728
#define AKV_OFF    (2*AQ_BYTES)        // 36864
#define ATT_SMEM   (AKV_OFF + 2*AKV_STAGE)   // 184320
#define L2E8 11.541560327111707f       // 8 * log2(e)

__device__ __forceinline__ void attn_cp_kv(
    uint32_t sbase, int st, const __nv_bfloat16* qkvh, const __nv_bfloat16* qkvl,
    size_t rowbase, int tid)
{
    int b = tid >> 6;           // 0:Kh 1:Kl 2:Vh 3:Vl
    int r0 = tid & 63;
    const __nv_bfloat16* base = ((b & 1) ? qkvl : qkvh)
        + rowbase + ((b >> 1) ? 2048 : 1024);
    uint32_t dbuf = sbase + AKV_OFF + st*AKV_STAGE + b*AKV_BUF;
#pragma unroll
    for (int half = 0; half < 2; half++) {
        int row = r0 + half*64;
        const __nv_bfloat16* src = base + (size_t)row * 3072;
        uint32_t dst = dbuf + row*AROW;
#pragma unroll
        for (int c = 0; c < 8; c++) cp16(dst + c*16, src + c*8);
    }
    cp_commit();
}

__global__ __launch_bounds__(256) void attn_fa2_kernel(
    const __nv_bfloat16* __restrict__ qkvh, const __nv_bfloat16* __restrict__ qkvl,
    __nv_bfloat16* __restrict__ atth, __nv_bfloat16* __restrict__ attl)
{
    extern __shared__ char smraw[];
    const uint32_t sbase = s2u(smraw);

    const int tid  = threadIdx.x;
    const int warp = tid >> 5;
    const int lid  = tid & 31;
    const int g    = lid >> 2;
    const int qr   = lid & 3;
    const int grp  = lid >> 3;
    const int rr   = lid & 7;

    const int qt = (gridDim.x - 1) - blockIdx.x;   // longest tiles first
    const int bh = blockIdx.y;
    const int b_ = bh >> 4;
    const int h  = bh & 15;
    const int t0 = qt * 128;

    // anti-phase: high warps visit sub-tiles in reverse order
    const int subflip = (warp >> 2) & 1;

    {
        int qb  = tid >> 7;
        int row = tid & 127;
        const __nv_bfloat16* src = (qb ? qkvl : qkvh)
            + (size_t)(b_*NT + t0 + row) * 3072 + h*HD;
        uint32_t dst = sbase + qb*AQ_BYTES + row*AROW;
#pragma unroll
        for (int c = 0; c < 8; c++) cp16(dst + c*16, src + c*8);
    }
    cp_commit();

    attn_cp_kv(sbase, 0, qkvh, qkvl, (size_t)(b_*NT) * 3072 + h*HD, tid);

    cp_wait1();
    __syncthreads();

    uint32_t aqh[4][4], aql[4][4];
    {
        uint32_t rowoff = (16*warp + ((grp & 1) ? 8 : 0) + rr) * AROW
                        + ((grp >= 2) ? 16 : 0);
#pragma unroll
        for (int kk = 0; kk < 4; kk++) {
            ldm4(aqh[kk][0], aqh[kk][1], aqh[kk][2], aqh[kk][3],
                 sbase + rowoff + kk*32);
            ldm4(aql[kk][0], aql[kk][1], aql[kk][2], aql[kk][3],
                 sbase + AQ_BYTES + rowoff + kk*32);
        }
    }

    float O[8][4];
#pragma unroll
    for (int nt = 0; nt < 8; nt++) {
        O[nt][0] = 0.f; O[nt][1] = 0.f; O[nt][2] = 0.f; O[nt][3] = 0.f;
    }
    // m: running row max (raw logit domain). l: per-thread PARTIAL row sum.
    float m0 = -1e30f, m1 = -1e30f, l0 = 0.f, l1 = 0.f;

    const int i0 = t0 + 16*warp + g;
    const int i1 = i0 + 8;
    const int njt = qt + 1;               // 128-row macro tiles

    const uint32_t k_rowsel = ((grp >= 2) ? 8 : 0) + rr;
    const uint32_t k_colsel = ((grp & 1) ? 16 : 0);
    const uint32_t v_rowsel = ((grp & 1) ? 8 : 0) + rr;
    const uint32_t v_colsel = ((grp >= 2) ? 16 : 0);

    for (int jt = 0; jt < njt; jt++) {
        const int st = jt & 1;
        if (jt + 1 < njt)
            attn_cp_kv(sbase, st ^ 1, qkvh, qkvl,
                       (size_t)(b_*NT + (jt+1)*128) * 3072 + h*HD, tid);
        if (jt + 1 < njt) cp_wait1(); else cp_wait0();
        __syncthreads();

        const uint32_t sStage = sbase + AKV_OFF + st*AKV_STAGE;
        const bool need_mask = (jt == qt);

#pragma unroll
        for (int subi = 0; subi < 2; subi++) {
            const int sub = subi ^ subflip;          // anti-phase ordering
            const uint32_t soff = sub * 64 * AROW;
            const uint32_t sKh = sStage + soff;
            const uint32_t sKl = sStage + AKV_BUF + soff;
            const uint32_t sVh = sStage + 2*AKV_BUF + soff;
            const uint32_t sVl = sStage + 3*AKV_BUF + soff;

            float S[8][4];
#pragma unroll
            for (int nt = 0; nt < 8; nt++) {
                S[nt][0] = 0.f; S[nt][1] = 0.f; S[nt][2] = 0.f; S[nt][3] = 0.f;
            }
#pragma unroll
            for (int kk = 0; kk < 4; kk++) {
#pragma unroll
                for (int np = 0; np < 4; np++) {
                    uint32_t addr = (np*16 + k_rowsel)*AROW + kk*32 + k_colsel;
                    uint32_t bh0, bh1, bh2, bh3, bl0, bl1, bl2, bl3;
                    ldm4(bh0, bh1, bh2, bh3, sKh + addr);
                    ldm4(bl0, bl1, bl2, bl3, sKl + addr);
                    mma_bf16(S[2*np],   aqh[kk][0], aqh[kk][1], aqh[kk][2], aqh[kk][3], bh0, bh1);
                    mma_bf16(S[2*np],   aqh[kk][0], aqh[kk][1], aqh[kk][2], aqh[kk][3], bl0, bl1);
                    mma_bf16(S[2*np],   aql[kk][0], aql[kk][1], aql[kk][2], aql[kk][3], bh0, bh1);
                    mma_bf16(S[2*np+1], aqh[kk][0], aqh[kk][1], aqh[kk][2], aqh[kk][3], bh2, bh3);
                    mma_bf16(S[2*np+1], aqh[kk][0], aqh[kk][1], aqh[kk][2], aqh[kk][3], bl2, bl3);
                    mma_bf16(S[2*np+1], aql[kk][0], aql[kk][1], aql[kk][2], aql[kk][3], bh2, bh3);
                }
            }

            // mask (raw logit domain; scale folded into exp2 below)
            if (need_mask) {
                const int jbase = jt*128 + sub*64;
#pragma unroll
                for (int nt = 0; nt < 8; nt++) {
                    int jb = jbase + nt*8 + qr*2;
                    if (jb     > i0) S[nt][0] = -1e30f;
                    if (jb + 1 > i0) S[nt][1] = -1e30f;
                    if (jb     > i1) S[nt][2] = -1e30f;
                    if (jb + 1 > i1) S[nt][3] = -1e30f;
                }
            }

            // row max (raw domain)
            float mx0 = -1e30f, mx1 = -1e30f;
#pragma unroll
            for (int nt = 0; nt < 8; nt++) {
                mx0 = fmaxf(mx0, fmaxf(S[nt][0], S[nt][1]));
                mx1 = fmaxf(mx1, fmaxf(S[nt][2], S[nt][3]));
            }
            mx0 = fmaxf(mx0, __shfl_xor_sync(0xffffffffu, mx0, 1));
            mx0 = fmaxf(mx0, __shfl_xor_sync(0xffffffffu, mx0, 2));
            mx1 = fmaxf(mx1, __shfl_xor_sync(0xffffffffu, mx1, 1));
            mx1 = fmaxf(mx1, __shfl_xor_sync(0xffffffffu, mx1, 2));

            float mn0 = fmaxf(m0, mx0), mn1 = fmaxf(m1, mx1);
            float corr0 = exp2f((m0 - mn0) * L2E8);
            float corr1 = exp2f((m1 - mn1) * L2E8);
            m0 = mn0; m1 = mn1;
            const float c0 = mn0 * L2E8;
            const float c1 = mn1 * L2E8;

            float sum0 = 0.f, sum1 = 0.f;
#pragma unroll
            for (int nt = 0; nt < 8; nt++) {
                float p0 = exp2f(fmaf(S[nt][0], L2E8, -c0));
                float p1 = exp2f(fmaf(S[nt][1], L2E8, -c0));
                float p2 = exp2f(fmaf(S[nt][2], L2E8, -c1));
                float p3 = exp2f(fmaf(S[nt][3], L2E8, -c1));
                sum0 += p0 + p1; sum1 += p2 + p3;
                S[nt][0] = p0; S[nt][1] = p1; S[nt][2] = p2; S[nt][3] = p3;
            }
            l0 = l0 * corr0 + sum0;
            l1 = l1 * corr1 + sum1;

#pragma unroll
            for (int nt = 0; nt < 8; nt++) {
                O[nt][0] *= corr0; O[nt][1] *= corr0;
                O[nt][2] *= corr1; O[nt][3] *= corr1;
            }

#pragma unroll
            for (int kk = 0; kk < 4; kk++) {
                uint32_t ah0, ah1, ah2, ah3, al0, al1, al2, al3;
                pack_hilo(S[2*kk][0],   S[2*kk][1],   ah0, al0);
                pack_hilo(S[2*kk][2],   S[2*kk][3],   ah1, al1);
                pack_hilo(S[2*kk+1][0], S[2*kk+1][1], ah2, al2);
                pack_hilo(S[2*kk+1][2], S[2*kk+1][3], ah3, al3);
#pragma unroll
                for (int np = 0; np < 4; np++) {
                    uint32_t addr = (kk*16 + v_rowsel)*AROW + np*32 + v_colsel;
                    uint32_t bh0, bh1, bh2, bh3, bl0, bl1, bl2, bl3;
                    ldm4t(bh0, bh1, bh2, bh3, sVh + addr);
                    ldm4t(bl0, bl1, bl2, bl3, sVl + addr);
                    mma_bf16(O[2*np],   ah0, ah1, ah2, ah3, bh0, bh1);
                    mma_bf16(O[2*np],   ah0, ah1, ah2, ah3, bl0, bl1);
                    mma_bf16(O[2*np],   al0, al1, al2, al3, bh0, bh1);
                    mma_bf16(O[2*np+1], ah0, ah1, ah2, ah3, bh2, bh3);
                    mma_bf16(O[2*np+1], ah0, ah1, ah2, ah3, bl2, bl3);
                    mma_bf16(O[2*np+1], al0, al1, al2, al3, bh2, bh3);
                }
            }
        }
        __syncthreads();
    }

    // final quad reduction of partial l, then normalize + store
    l0 += __shfl_xor_sync(0xffffffffu, l0, 1);
    l0 += __shfl_xor_sync(0xffffffffu, l0, 2);
    l1 += __shfl_xor_sync(0xffffffffu, l1, 1);
    l1 += __shfl_xor_sync(0xffffffffu, l1, 2);

    float inv0 = 1.f / l0, inv1 = 1.f / l1;
    size_t r0 = (size_t)(b_*NT + i0) * NC + h*HD + qr*2;
    size_t r1 = (size_t)(b_*NT + i1) * NC + h*HD + qr*2;
#pragma unroll
    for (int nt = 0; nt < 8; nt++) {
        split_store2(O[nt][0]*inv0, O[nt][1]*inv0, atth + r0 + nt*8, attl + r0 + nt*8);
        split_store2(O[nt][2]*inv1, O[nt][3]*inv1, atth + r1 + nt*8, attl + r1 + nt*8);
    }
}

// ---------------------------------------------------------------------------

extern "C" void kernel_launch(void* const* d_in, const int* in_sizes, int n_in,
                              void* d_out, int out_size)
{
    const float* x      = (const float*)d_in[0];
    const float* W_attn = (const float*)d_in[1];
    const float* W_proj = (const float*)d_in[2];
    const float* b_proj = (const float*)d_in[3];
    float* out = (float*)d_out;

    __nv_bfloat16 *xh, *xl, *wah, *wal, *wph, *wpl, *qkvh, *qkvl, *atth, *attl;
    cudaGetSymbolAddress((void**)&xh,   g_xh);
    cudaGetSymbolAddress((void**)&xl,   g_xl);
    cudaGetSymbolAddress((void**)&wah,  g_wah);
    cudaGetSymbolAddress((void**)&wal,  g_wal);
    cudaGetSymbolAddress((void**)&wph,  g_wph);
    cudaGetSymbolAddress((void**)&wpl,  g_wpl);
    cudaGetSymbolAddress((void**)&qkvh, g_qkvh);
    cudaGetSymbolAddress((void**)&qkvl, g_qkvl);
    cudaGetSymbolAddress((void**)&atth, g_atth);
    cudaGetSymbolAddress((void**)&attl, g_attl);

    cudaFuncSetAttribute(gemm_mma_kernel,
                         cudaFuncAttributeMaxDynamicSharedMemorySize, GEMM_SMEM);
    cudaFuncSetAttribute(attn_fa2_kernel,
                         cudaFuncAttributeMaxDynamicSharedMemorySize, ATT_SMEM);

    split_kernel<<<8192, 256>>>((const float4*)x,      xh,  xl,  2097152);
    split_kernel<<<3072, 256>>>((const float4*)W_attn, wah, wal, 786432);
    split_kernel<<<1024, 256>>>((const float4*)W_proj, wph, wpl, 262144);

    // QKV: [8192,1024] x [3072,1024]^T -> bf16 hi/lo
    gemm_mma_kernel<<<dim3(12, 64), 256, GEMM_SMEM>>>(
        xh, xl, wah, wal, qkvh, qkvl, nullptr, nullptr, 3072, 0);

    // attention: 128-row q tiles, kv macro 128, anti-phase sub scheduling
    attn_fa2_kernel<<<dim3(16, 64), 256, ATT_SMEM>>>(qkvh, qkvl, atth, attl);

    // proj: [8192,1024] x [1024,1024]^T + bias -> f32 out
    gemm_mma_kernel<<<dim3(4, 64), 256, GEMM_SMEM>>>(
        atth, attl, wph, wpl, nullptr, nullptr, out, b_proj, 1024, 1);
}

// round 13
// speedup vs baseline: 1.0594x; 1.0594x over previous
#include <cuda_runtime.h>
#include <cuda_bf16.h>
#include <math.h>
#include <cstdint>

#define NB 4
#define NT 2048
#define NC 1024
#define NH 16
#define HD 64
#define MM (NB*NT)          // 8192

// ---------------- global scratch (device globals; no runtime alloc) --------
__device__ __nv_bfloat16 g_xh[(size_t)MM*NC],    g_xl[(size_t)MM*NC];
__device__ __nv_bfloat16 g_wah[(size_t)3*NC*NC], g_wal[(size_t)3*NC*NC];
__device__ __nv_bfloat16 g_wph[(size_t)NC*NC],   g_wpl[(size_t)NC*NC];
__device__ __nv_bfloat16 g_qkvh[(size_t)MM*3*NC],g_qkvl[(size_t)MM*3*NC];
__device__ __nv_bfloat16 g_atth[(size_t)MM*NC],  g_attl[(size_t)MM*NC];

// ---------------- helpers --------------------------------------------------
__device__ __forceinline__ uint32_t s2u(const void* p) {
    return (uint32_t)__cvta_generic_to_shared(p);
}
__device__ __forceinline__ void cp16(uint32_t dst, const void* src) {
    asm volatile("cp.async.cg.shared.global [%0], [%1], 16;" :: "r"(dst), "l"(src));
}
__device__ __forceinline__ void cp_commit() {
    asm volatile("cp.async.commit_group;" ::: "memory");
}
__device__ __forceinline__ void cp_wait1() {
    asm volatile("cp.async.wait_group 1;" ::: "memory");
}
__device__ __forceinline__ void cp_wait0() {
    asm volatile("cp.async.wait_group 0;" ::: "memory");
}
__device__ __forceinline__ void ldm4(uint32_t& r0, uint32_t& r1, uint32_t& r2,
                                     uint32_t& r3, uint32_t a) {
    asm volatile("ldmatrix.sync.aligned.m8n8.x4.shared.b16 {%0,%1,%2,%3}, [%4];"
                 : "=r"(r0), "=r"(r1), "=r"(r2), "=r"(r3) : "r"(a));
}
__device__ __forceinline__ void ldm4t(uint32_t& r0, uint32_t& r1, uint32_t& r2,
                                      uint32_t& r3, uint32_t a) {
    asm volatile("ldmatrix.sync.aligned.m8n8.x4.trans.shared.b16 {%0,%1,%2,%3}, [%4];"
                 : "=r"(r0), "=r"(r1), "=r"(r2), "=r"(r3) : "r"(a));
}
__device__ __forceinline__ void mma_bf16(float* c, uint32_t a0, uint32_t a1,
                                         uint32_t a2, uint32_t a3,
                                         uint32_t b0, uint32_t b1) {
    asm volatile("mma.sync.aligned.m16n8k16.row.col.f32.bf16.bf16.f32 "
                 "{%0,%1,%2,%3}, {%4,%5,%6,%7}, {%8,%9}, {%0,%1,%2,%3};"
                 : "+f"(c[0]), "+f"(c[1]), "+f"(c[2]), "+f"(c[3])
                 : "r"(a0), "r"(a1), "r"(a2), "r"(a3), "r"(b0), "r"(b1));
}

// Fast split: one cvt.rn.bf16x2 per pair (identical RN rounding to the
// scalar path), residual reconstruction via integer shifts (ALU pipe).
__device__ __forceinline__ void pack_hilo(float x, float y, uint32_t& h, uint32_t& l)
{
    asm("cvt.rn.bf16x2.f32 %0, %1, %2;" : "=r"(h) : "f"(y), "f"(x));
    float hx = __uint_as_float(h << 16);
    float hy = __uint_as_float(h & 0xFFFF0000u);
    float rx = x - hx;
    float ry = y - hy;
    asm("cvt.rn.bf16x2.f32 %0, %1, %2;" : "=r"(l) : "f"(ry), "f"(rx));
}
__device__ __forceinline__ void split_store2(float x, float y,
                                             __nv_bfloat16* hp, __nv_bfloat16* lp)
{
    uint32_t h, l;
    pack_hilo(x, y, h, l);
    *(uint32_t*)hp = h;
    *(uint32_t*)lp = l;
}

// f32x2 packed multiply: (a,b) *= k
__device__ __forceinline__ void mul2pair(float& a, float& b, uint64_t kk)
{
    uint64_t v, r;
    asm("mov.b64 %0, {%1, %2};" : "=l"(v) : "f"(a), "f"(b));
    asm("mul.rn.f32x2 %0, %1, %2;" : "=l"(r) : "l"(v), "l"(kk));
    asm("mov.b64 {%0, %1}, %2;" : "=f"(a), "=f"(b) : "l"(r));
}
__device__ __forceinline__ uint64_t bcast2(float k)
{
    uint64_t r;
    asm("mov.b64 %0, {%1, %1};" : "=l"(r) : "f"(k));
    return r;
}

// ---------------- split kernel (f32 -> bf16 hi/lo) -------------------------
__global__ __launch_bounds__(256) void split_kernel(
    const float4* __restrict__ src, __nv_bfloat16* __restrict__ dh,
    __nv_bfloat16* __restrict__ dl, int n4)
{
    int i = blockIdx.x * 256 + threadIdx.x;
    if (i >= n4) return;
    float4 v = src[i];
    split_store2(v.x, v.y, dh + (size_t)i*4,     dl + (size_t)i*4);
    split_store2(v.z, v.w, dh + (size_t)i*4 + 2, dl + (size_t)i*4 + 2);
}

// ---------------------------------------------------------------------------
// mma.sync GEMM on pre-split bf16: C = A * B^T, K=1024. Templated on BN.
// CTA 128xBN, 8 warps (warp = 64 x BN/4), BK=64, 2-stage, split prefetch.
// BN=192 for QKV (wave-quantization fix: 1024 CTAs = 6.92 waves),
// BN=256 for proj.
// ---------------------------------------------------------------------------
#define GROW 144
#define GABUF (128*GROW)            // 18432

template<int BN>
__device__ __forceinline__ void g_load_A(
    uint32_t sbase, int st, int kt, int m0, int tid,
    const __nv_bfloat16* __restrict__ Ah, const __nv_bfloat16* __restrict__ Al)
{
    constexpr int GSTG = 2*GABUF + 2*BN*GROW;
    const int koff = kt * 64;
    const uint32_t dbase = sbase + st * GSTG;
#pragma unroll
    for (int i = 0; i < 4; i++) {
        int gidx = i * 256 + tid;
        int row = gidx >> 3, c = gidx & 7;
        uint32_t doff = row * GROW + c * 16;
        size_t soff = (size_t)(m0 + row) * 1024 + koff + c * 8;
        cp16(dbase + doff,         Ah + soff);
        cp16(dbase + GABUF + doff, Al + soff);
    }
}
template<int BN>
__device__ __forceinline__ void g_load_B(
    uint32_t sbase, int st, int kt, int n0, int tid,
    const __nv_bfloat16* __restrict__ Bh, const __nv_bfloat16* __restrict__ Bl)
{
    constexpr int GSTG = 2*GABUF + 2*BN*GROW;
    constexpr int GBBUF = BN*GROW;
    const int koff = kt * 64;
    const uint32_t dbase = sbase + st * GSTG + 2*GABUF;
#pragma unroll
    for (int i = 0; i < BN/32; i++) {
        int gidx = i * 256 + tid;
        int row = gidx >> 3, c = gidx & 7;
        uint32_t doff = row * GROW + c * 16;
        size_t soff = (size_t)(n0 + row) * 1024 + koff + c * 8;
        cp16(dbase + doff,         Bh + soff);
        cp16(dbase + GBBUF + doff, Bl + soff);
    }
}

template<int BN>
__global__ __launch_bounds__(256, 1) void gemm_mma_kernel(
    const __nv_bfloat16* __restrict__ Ah, const __nv_bfloat16* __restrict__ Al,
    const __nv_bfloat16* __restrict__ Bh, const __nv_bfloat16* __restrict__ Bl,
    __nv_bfloat16* __restrict__ outH, __nv_bfloat16* __restrict__ outL,
    float* __restrict__ outF, const float* __restrict__ bias,
    int ldc, int mode)
{
    constexpr int GBBUF = BN*GROW;
    constexpr int GSTG  = 2*GABUF + 2*GBBUF;
    constexpr int WN    = BN/4;      // warp n-width (64 or 48)
    constexpr int NCN   = WN/16;     // 4 or 3
    constexpr int ELD   = BN + 4;

    extern __shared__ char sm[];
    const uint32_t sbase = s2u(sm);
    const int tid  = threadIdx.x;
    const int warp = tid >> 5;
    const int lid  = tid & 31;
    const int g    = lid >> 2;
    const int qr   = lid & 3;
    const int grp  = lid >> 3;
    const int rr   = lid & 7;

    const int m0 = blockIdx.y << 7;
    const int n0 = blockIdx.x * BN;
    const int mw = (warp >> 2) * 64;
    const int nw = (warp & 3) * WN;

    const uint32_t a_rowsel = ((grp & 1) ? 8 : 0) + rr;
    const uint32_t a_colsel = (grp >= 2) ? 16 : 0;
    const uint32_t b_rowsel = ((grp >= 2) ? 8 : 0) + rr;
    const uint32_t b_colsel = (grp & 1) ? 16 : 0;

    float acc[4][2*NCN][4];
#pragma unroll
    for (int mt = 0; mt < 4; mt++)
#pragma unroll
        for (int nt = 0; nt < 2*NCN; nt++) {
            acc[mt][nt][0] = 0.f; acc[mt][nt][1] = 0.f;
            acc[mt][nt][2] = 0.f; acc[mt][nt][3] = 0.f;
        }

    g_load_A<BN>(sbase, 0, 0, m0, tid, Ah, Al);
    g_load_B<BN>(sbase, 0, 0, n0, tid, Bh, Bl);
    cp_commit();

    int stidx = 0;
    for (int kt = 0; kt < 16; kt++) {
        cp_wait0();
        __syncthreads();

        const uint32_t sb  = sbase + stidx * GSTG;
        const uint32_t sAh = sb;
        const uint32_t sAl = sb + GABUF;
        const uint32_t sBh = sb + 2*GABUF;
        const uint32_t sBl = sb + 2*GABUF + GBBUF;

        if (kt + 1 < 16)
            g_load_A<BN>(sbase, stidx ^ 1, kt + 1, m0, tid, Ah, Al);

#pragma unroll
        for (int half = 0; half < 2; half++) {
#pragma unroll
            for (int kq = 0; kq < 2; kq++) {
                const int kk = half*2 + kq;
                uint32_t ah[4][4], al[4][4];
#pragma unroll
                for (int mt = 0; mt < 4; mt++) {
                    uint32_t ra = (mw + mt*16 + a_rowsel) * GROW + kk*32 + a_colsel;
                    ldm4(ah[mt][0], ah[mt][1], ah[mt][2], ah[mt][3], sAh + ra);
                    ldm4(al[mt][0], al[mt][1], al[mt][2], al[mt][3], sAl + ra);
                }
#pragma unroll
                for (int nc = 0; nc < NCN; nc++) {
                    uint32_t rb = (nw + nc*16 + b_rowsel) * GROW + kk*32 + b_colsel;
                    uint32_t bh0, bh1, bh2, bh3, bl0, bl1, bl2, bl3;
                    ldm4(bh0, bh1, bh2, bh3, sBh + rb);
                    ldm4(bl0, bl1, bl2, bl3, sBl + rb);
#pragma unroll
                    for (int mt = 0; mt < 4; mt++) {
                        mma_bf16(acc[mt][2*nc],   ah[mt][0], ah[mt][1], ah[mt][2], ah[mt][3], bh0, bh1);
                        mma_bf16(acc[mt][2*nc+1], ah[mt][0], ah[mt][1], ah[mt][2], ah[mt][3], bh2, bh3);
                    }
#pragma unroll
                    for (int mt = 0; mt < 4; mt++) {
                        mma_bf16(acc[mt][2*nc],   ah[mt][0], ah[mt][1], ah[mt][2], ah[mt][3], bl0, bl1);
                        mma_bf16(acc[mt][2*nc+1], ah[mt][0], ah[mt][1], ah[mt][2], ah[mt][3], bl2, bl3);
                    }
#pragma unroll
                    for (int mt = 0; mt < 4; mt++) {
                        mma_bf16(acc[mt][2*nc],   al[mt][0], al[mt][1], al[mt][2], al[mt][3], bh0, bh1);
                        mma_bf16(acc[mt][2*nc+1], al[mt][0], al[mt][1], al[mt][2], al[mt][3], bh2, bh3);
                    }
                }
            }
            if (half == 0) {
                if (kt + 1 < 16)
                    g_load_B<BN>(sbase, stidx ^ 1, kt + 1, n0, tid, Bh, Bl);
                cp_commit();
            }
        }
        stidx ^= 1;
    }

    __syncthreads();
    float* Sst = (float*)sm;
#pragma unroll
    for (int mt = 0; mt < 4; mt++) {
        int row = mw + mt*16 + g;
#pragma unroll
        for (int nt = 0; nt < 2*NCN; nt++) {
            int col = nw + nt*8 + qr*2;
            *(float2*)&Sst[row*ELD + col]       = make_float2(acc[mt][nt][0], acc[mt][nt][1]);
            *(float2*)&Sst[(row+8)*ELD + col]   = make_float2(acc[mt][nt][2], acc[mt][nt][3]);
        }
    }
    __syncthreads();

    if (mode == 0) {
#pragma unroll 1
        for (int r = 0; r < 16; r++) {
            int row = warp*16 + r;
            size_t ob = (size_t)(m0 + row) * ldc + n0;
#pragma unroll
            for (int blk = 0; blk < BN/64; blk++) {
                int c = blk*64 + lid*2;
                float2 v = *(float2*)&Sst[row*ELD + c];
                split_store2(v.x, v.y, outH + ob + c, outL + ob + c);
            }
        }
    } else {
#pragma unroll 1
        for (int r = 0; r < 16; r++) {
            int row = warp*16 + r;
            size_t ob = (size_t)(m0 + row) * ldc + n0;
#pragma unroll
            for (int blk = 0; blk < BN/128; blk++) {
                int c = blk*128 + lid*4;
                float4 v = *(float4*)&Sst[row*ELD + c];
                v.x += bias[n0 + c];     v.y += bias[n0 + c + 1];
                v.z += bias[n0 + c + 2]; v.w += bias[n0 + c + 3];
                *(float4*)(outF + ob + c) = v;
            }
        }
    }
}

// ---------------------------------------------------------------------------
// Register-resident flash attention (R10 structure). 128 q rows, 8 warps,
// kv macro-tile 128 (2x64 subs). exp2-folded softmax, deferred l-reduction,
// f32x2 O-rescale, single-cvt bf16x2 packing.
// ---------------------------------------------------------------------------
#define AROW 144
#define AQ_BYTES   (128*AROW)          // 18432
#define AKV_BUF    (128*AROW)          // 18432 per tensor buffer
#define AKV_STAGE  (4*AKV_BUF)         // 73728
#define AKV_OFF    (2*AQ_BYTES)        // 36864
#define ATT_SMEM   (AKV_OFF + 2*AKV_STAGE)   // 184320
#define L2E8 11.541560327111707f       // 8 * log2(e)

__device__ __forceinline__ void attn_cp_kv(
    uint32_t sbase, int st, const __nv_bfloat16* qkvh, const __nv_bfloat16* qkvl,
    size_t rowbase, int tid)
{
    int b = tid >> 6;           // 0:Kh 1:Kl 2:Vh 3:Vl
    int r0 = tid & 63;
    const __nv_bfloat16* base = ((b & 1) ? qkvl : qkvh)
        + rowbase + ((b >> 1) ? 2048 : 1024);
    uint32_t dbuf = sbase + AKV_OFF + st*AKV_STAGE + b*AKV_BUF;
#pragma unroll
    for (int half = 0; half < 2; half++) {
        int row = r0 + half*64;
        const __nv_bfloat16* src = base + (size_t)row * 3072;
        uint32_t dst = dbuf + row*AROW;
#pragma unroll
        for (int c = 0; c < 8; c++) cp16(dst + c*16, src + c*8);
    }
    cp_commit();
}

__global__ __launch_bounds__(256) void attn_fa2_kernel(
    const __nv_bfloat16* __restrict__ qkvh, const __nv_bfloat16* __restrict__ qkvl,
    __nv_bfloat16* __restrict__ atth, __nv_bfloat16* __restrict__ attl)
{
    extern __shared__ char smraw[];
    const uint32_t sbase = s2u(smraw);

    const int tid  = threadIdx.x;
    const int warp = tid >> 5;
    const int lid  = tid & 31;
    const int g    = lid >> 2;
    const int qr   = lid & 3;
    const int grp  = lid >> 3;
    const int rr   = lid & 7;

    const int qt = (gridDim.x - 1) - blockIdx.x;   // longest tiles first
    const int bh = blockIdx.y;
    const int b_ = bh >> 4;
    const int h  = bh & 15;
    const int t0 = qt * 128;

    {
        int qb  = tid >> 7;
        int row = tid & 127;
        const __nv_bfloat16* src = (qb ? qkvl : qkvh)
            + (size_t)(b_*NT + t0 + row) * 3072 + h*HD;
        uint32_t dst = sbase + qb*AQ_BYTES + row*AROW;
#pragma unroll
        for (int c = 0; c < 8; c++) cp16(dst + c*16, src + c*8);
    }
    cp_commit();

    attn_cp_kv(sbase, 0, qkvh, qkvl, (size_t)(b_*NT) * 3072 + h*HD, tid);

    cp_wait1();
    __syncthreads();

    uint32_t aqh[4][4], aql[4][4];
    {
        uint32_t rowoff = (16*warp + ((grp & 1) ? 8 : 0) + rr) * AROW
                        + ((grp >= 2) ? 16 : 0);
#pragma unroll
        for (int kk = 0; kk < 4; kk++) {
            ldm4(aqh[kk][0], aqh[kk][1], aqh[kk][2], aqh[kk][3],
                 sbase + rowoff + kk*32);
            ldm4(aql[kk][0], aql[kk][1], aql[kk][2], aql[kk][3],
                 sbase + AQ_BYTES + rowoff + kk*32);
        }
    }

    float O[8][4];
#pragma unroll
    for (int nt = 0; nt < 8; nt++) {
        O[nt][0] = 0.f; O[nt][1] = 0.f; O[nt][2] = 0.f; O[nt][3] = 0.f;
    }
    float m0 = -1e30f, m1 = -1e30f, l0 = 0.f, l1 = 0.f;

    const int i0 = t0 + 16*warp + g;
    const int i1 = i0 + 8;
    const int njt = qt + 1;               // 128-row macro tiles

    const uint32_t k_rowsel = ((grp >= 2) ? 8 : 0) + rr;
    const uint32_t k_colsel = ((grp & 1) ? 16 : 0);
    const uint32_t v_rowsel = ((grp & 1) ? 8 : 0) + rr;
    const uint32_t v_colsel = ((grp >= 2) ? 16 : 0);

    for (int jt = 0; jt < njt; jt++) {
        const int st = jt & 1;
        if (jt + 1 < njt)
            attn_cp_kv(sbase, st ^ 1, qkvh, qkvl,
                       (size_t)(b_*NT + (jt+1)*128) * 3072 + h*HD, tid);
        if (jt + 1 < njt) cp_wait1(); else cp_wait0();
        __syncthreads();

        const uint32_t sStage = sbase + AKV_OFF + st*AKV_STAGE;
        const bool need_mask = (jt == qt);

#pragma unroll
        for (int sub = 0; sub < 2; sub++) {
            const uint32_t soff = sub * 64 * AROW;
            const uint32_t sKh = sStage + soff;
            const uint32_t sKl = sStage + AKV_BUF + soff;
            const uint32_t sVh = sStage + 2*AKV_BUF + soff;
            const uint32_t sVl = sStage + 3*AKV_BUF + soff;

            float S[8][4];
#pragma unroll
            for (int nt = 0; nt < 8; nt++) {
                S[nt][0] = 0.f; S[nt][1] = 0.f; S[nt][2] = 0.f; S[nt][3] = 0.f;
            }
#pragma unroll
            for (int kk = 0; kk < 4; kk++) {
#pragma unroll
                for (int np = 0; np < 4; np++) {
                    uint32_t addr = (np*16 + k_rowsel)*AROW + kk*32 + k_colsel;
                    uint32_t bh0, bh1, bh2, bh3, bl0, bl1, bl2, bl3;
                    ldm4(bh0, bh1, bh2, bh3, sKh + addr);
                    ldm4(bl0, bl1, bl2, bl3, sKl + addr);
                    mma_bf16(S[2*np],   aqh[kk][0], aqh[kk][1], aqh[kk][2], aqh[kk][3], bh0, bh1);
                    mma_bf16(S[2*np],   aqh[kk][0], aqh[kk][1], aqh[kk][2], aqh[kk][3], bl0, bl1);
                    mma_bf16(S[2*np],   aql[kk][0], aql[kk][1], aql[kk][2], aql[kk][3], bh0, bh1);
                    mma_bf16(S[2*np+1], aqh[kk][0], aqh[kk][1], aqh[kk][2], aqh[kk][3], bh2, bh3);
                    mma_bf16(S[2*np+1], aqh[kk][0], aqh[kk][1], aqh[kk][2], aqh[kk][3], bl2, bl3);
                    mma_bf16(S[2*np+1], aql[kk][0], aql[kk][1], aql[kk][2], aql[kk][3], bh2, bh3);
                }
            }

            if (need_mask) {
                const int jbase = jt*128 + sub*64;
#pragma unroll
                for (int nt = 0; nt < 8; nt++) {
                    int jb = jbase + nt*8 + qr*2;
                    if (jb     > i0) S[nt][0] = -1e30f;
                    if (jb + 1 > i0) S[nt][1] = -1e30f;
                    if (jb     > i1) S[nt][2] = -1e30f;
                    if (jb + 1 > i1) S[nt][3] = -1e30f;
                }
            }

            float mx0 = -1e30f, mx1 = -1e30f;
#pragma unroll
            for (int nt = 0; nt < 8; nt++) {
                mx0 = fmaxf(mx0, fmaxf(S[nt][0], S[nt][1]));
                mx1 = fmaxf(mx1, fmaxf(S[nt][2], S[nt][3]));
            }
            mx0 = fmaxf(mx0, __shfl_xor_sync(0xffffffffu, mx0, 1));
            mx0 = fmaxf(mx0, __shfl_xor_sync(0xffffffffu, mx0, 2));
            mx1 = fmaxf(mx1, __shfl_xor_sync(0xffffffffu, mx1, 1));
            mx1 = fmaxf(mx1, __shfl_xor_sync(0xffffffffu, mx1, 2));

            float mn0 = fmaxf(m0, mx0), mn1 = fmaxf(m1, mx1);
            float corr0 = exp2f((m0 - mn0) * L2E8);
            float corr1 = exp2f((m1 - mn1) * L2E8);
            m0 = mn0; m1 = mn1;
            const float c0 = mn0 * L2E8;
            const float c1 = mn1 * L2E8;

            float sum0 = 0.f, sum1 = 0.f;
#pragma unroll
            for (int nt = 0; nt < 8; nt++) {
                float p0 = exp2f(fmaf(S[nt][0], L2E8, -c0));
                float p1 = exp2f(fmaf(S[nt][1], L2E8, -c0));
                float p2 = exp2f(fmaf(S[nt][2], L2E8, -c1));
                float p3 = exp2f(fmaf(S[nt][3], L2E8, -c1));
                sum0 += p0 + p1; sum1 += p2 + p3;
                S[nt][0] = p0; S[nt][1] = p1; S[nt][2] = p2; S[nt][3] = p3;
            }
            l0 = l0 * corr0 + sum0;
            l1 = l1 * corr1 + sum1;

            // f32x2 packed O-rescale
            {
                uint64_t cc0 = bcast2(corr0), cc1 = bcast2(corr1);
#pragma unroll
                for (int nt = 0; nt < 8; nt++) {
                    mul2pair(O[nt][0], O[nt][1], cc0);
                    mul2pair(O[nt][2], O[nt][3], cc1);
                }
            }

#pragma unroll
            for (int kk = 0; kk < 4; kk++) {
                uint32_t ah0, ah1, ah2, ah3, al0, al1, al2, al3;
                pack_hilo(S[2*kk][0],   S[2*kk][1],   ah0, al0);
                pack_hilo(S[2*kk][2],   S[2*kk][3],   ah1, al1);
                pack_hilo(S[2*kk+1][0], S[2*kk+1][1], ah2, al2);
                pack_hilo(S[2*kk+1][2], S[2*kk+1][3], ah3, al3);
#pragma unroll
                for (int np = 0; np < 4; np++) {
                    uint32_t addr = (kk*16 + v_rowsel)*AROW + np*32 + v_colsel;
                    uint32_t bh0, bh1, bh2, bh3, bl0, bl1, bl2, bl3;
                    ldm4t(bh0, bh1, bh2, bh3, sVh + addr);
                    ldm4t(bl0, bl1, bl2, bl3, sVl + addr);
                    mma_bf16(O[2*np],   ah0, ah1, ah2, ah3, bh0, bh1);
                    mma_bf16(O[2*np],   ah0, ah1, ah2, ah3, bl0, bl1);
                    mma_bf16(O[2*np],   al0, al1, al2, al3, bh0, bh1);
                    mma_bf16(O[2*np+1], ah0, ah1, ah2, ah3, bh2, bh3);
                    mma_bf16(O[2*np+1], ah0, ah1, ah2, ah3, bl2, bl3);
                    mma_bf16(O[2*np+1], al0, al1, al2, al3, bh2, bh3);
                }
            }
        }
        __syncthreads();
    }

    // final quad reduction of partial l, then normalize + store
    l0 += __shfl_xor_sync(0xffffffffu, l0, 1);
    l0 += __shfl_xor_sync(0xffffffffu, l0, 2);
    l1 += __shfl_xor_sync(0xffffffffu, l1, 1);
    l1 += __shfl_xor_sync(0xffffffffu, l1, 2);

    float inv0 = 1.f / l0, inv1 = 1.f / l1;
    size_t r0 = (size_t)(b_*NT + i0) * NC + h*HD + qr*2;
    size_t r1 = (size_t)(b_*NT + i1) * NC + h*HD + qr*2;
#pragma unroll
    for (int nt = 0; nt < 8; nt++) {
        split_store2(O[nt][0]*inv0, O[nt][1]*inv0, atth + r0 + nt*8, attl + r0 + nt*8);
        split_store2(O[nt][2]*inv1, O[nt][3]*inv1, atth + r1 + nt*8, attl + r1 + nt*8);
    }
}

// ---------------------------------------------------------------------------

extern "C" void kernel_launch(void* const* d_in, const int* in_sizes, int n_in,
                              void* d_out, int out_size)
{
    const float* x      = (const float*)d_in[0];
    const float* W_attn = (const float*)d_in[1];
    const float* W_proj = (const float*)d_in[2];
    const float* b_proj = (const float*)d_in[3];
    float* out = (float*)d_out;

    __nv_bfloat16 *xh, *xl, *wah, *wal, *wph, *wpl, *qkvh, *qkvl, *atth, *attl;
    cudaGetSymbolAddress((void**)&xh,   g_xh);
    cudaGetSymbolAddress((void**)&xl,   g_xl);
    cudaGetSymbolAddress((void**)&wah,  g_wah);
    cudaGetSymbolAddress((void**)&wal,  g_wal);
    cudaGetSymbolAddress((void**)&wph,  g_wph);
    cudaGetSymbolAddress((void**)&wpl,  g_wpl);
    cudaGetSymbolAddress((void**)&qkvh, g_qkvh);
    cudaGetSymbolAddress((void**)&qkvl, g_qkvl);
    cudaGetSymbolAddress((void**)&atth, g_atth);
    cudaGetSymbolAddress((void**)&attl, g_attl);

    constexpr int SM192 = 2*(2*GABUF + 2*192*GROW);   // 184320
    constexpr int SM256 = 2*(2*GABUF + 2*256*GROW);   // 221184

    cudaFuncSetAttribute(gemm_mma_kernel<192>,
                         cudaFuncAttributeMaxDynamicSharedMemorySize, SM192);
    cudaFuncSetAttribute(gemm_mma_kernel<256>,
                         cudaFuncAttributeMaxDynamicSharedMemorySize, SM256);
    cudaFuncSetAttribute(attn_fa2_kernel,
                         cudaFuncAttributeMaxDynamicSharedMemorySize, ATT_SMEM);

    split_kernel<<<8192, 256>>>((const float4*)x,      xh,  xl,  2097152);
    split_kernel<<<3072, 256>>>((const float4*)W_attn, wah, wal, 786432);
    split_kernel<<<1024, 256>>>((const float4*)W_proj, wph, wpl, 262144);

    // QKV: [8192,1024] x [3072,1024]^T -> bf16 hi/lo.  BN=192: 16x64 = 1024
    // CTAs = 6.92 waves (vs 5.19 at BN=256 -> 6-round makespan).
    gemm_mma_kernel<192><<<dim3(16, 64), 256, SM192>>>(
        xh, xl, wah, wal, qkvh, qkvl, nullptr, nullptr, 3072, 0);

    // attention: 128-row q tiles, kv macro 128
    attn_fa2_kernel<<<dim3(16, 64), 256, ATT_SMEM>>>(qkvh, qkvl, atth, attl);

    // proj: [8192,1024] x [1024,1024]^T + bias -> f32 out
    gemm_mma_kernel<256><<<dim3(4, 64), 256, SM256>>>(
        atth, attl, wph, wpl, nullptr, nullptr, out, b_proj, 1024, 1);
}

// round 14
// speedup vs baseline: 1.0681x; 1.0082x over previous
#include <cuda_runtime.h>
#include <cuda_bf16.h>
#include <math.h>
#include <cstdint>

#define NB 4
#define NT 2048
#define NC 1024
#define NH 16
#define HD 64
#define MM (NB*NT)          // 8192

// ---------------- global scratch (device globals; no runtime alloc) --------
__device__ __nv_bfloat16 g_xh[(size_t)MM*NC],    g_xl[(size_t)MM*NC];
__device__ __nv_bfloat16 g_wah[(size_t)3*NC*NC], g_wal[(size_t)3*NC*NC];
__device__ __nv_bfloat16 g_wph[(size_t)NC*NC],   g_wpl[(size_t)NC*NC];
__device__ __nv_bfloat16 g_qkvh[(size_t)MM*3*NC],g_qkvl[(size_t)MM*3*NC];
__device__ __nv_bfloat16 g_atth[(size_t)MM*NC],  g_attl[(size_t)MM*NC];

// ---------------- helpers --------------------------------------------------
__device__ __forceinline__ uint32_t s2u(const void* p) {
    return (uint32_t)__cvta_generic_to_shared(p);
}
__device__ __forceinline__ void cp16(uint32_t dst, const void* src) {
    asm volatile("cp.async.cg.shared.global [%0], [%1], 16;" :: "r"(dst), "l"(src));
}
__device__ __forceinline__ void cp_commit() {
    asm volatile("cp.async.commit_group;" ::: "memory");
}
__device__ __forceinline__ void cp_wait1() {
    asm volatile("cp.async.wait_group 1;" ::: "memory");
}
__device__ __forceinline__ void cp_wait0() {
    asm volatile("cp.async.wait_group 0;" ::: "memory");
}
__device__ __forceinline__ void ldm4(uint32_t& r0, uint32_t& r1, uint32_t& r2,
                                     uint32_t& r3, uint32_t a) {
    asm volatile("ldmatrix.sync.aligned.m8n8.x4.shared.b16 {%0,%1,%2,%3}, [%4];"
                 : "=r"(r0), "=r"(r1), "=r"(r2), "=r"(r3) : "r"(a));
}
__device__ __forceinline__ void ldm4t(uint32_t& r0, uint32_t& r1, uint32_t& r2,
                                      uint32_t& r3, uint32_t a) {
    asm volatile("ldmatrix.sync.aligned.m8n8.x4.trans.shared.b16 {%0,%1,%2,%3}, [%4];"
                 : "=r"(r0), "=r"(r1), "=r"(r2), "=r"(r3) : "r"(a));
}
__device__ __forceinline__ void mma_bf16(float* c, uint32_t a0, uint32_t a1,
                                         uint32_t a2, uint32_t a3,
                                         uint32_t b0, uint32_t b1) {
    asm volatile("mma.sync.aligned.m16n8k16.row.col.f32.bf16.bf16.f32 "
                 "{%0,%1,%2,%3}, {%4,%5,%6,%7}, {%8,%9}, {%0,%1,%2,%3};"
                 : "+f"(c[0]), "+f"(c[1]), "+f"(c[2]), "+f"(c[3])
                 : "r"(a0), "r"(a1), "r"(a2), "r"(a3), "r"(b0), "r"(b1));
}

// Fast split: one cvt.rn.bf16x2 per pair; residual via integer shifts.
__device__ __forceinline__ void pack_hilo(float x, float y, uint32_t& h, uint32_t& l)
{
    asm("cvt.rn.bf16x2.f32 %0, %1, %2;" : "=r"(h) : "f"(y), "f"(x));
    float hx = __uint_as_float(h << 16);
    float hy = __uint_as_float(h & 0xFFFF0000u);
    float rx = x - hx;
    float ry = y - hy;
    asm("cvt.rn.bf16x2.f32 %0, %1, %2;" : "=r"(l) : "f"(ry), "f"(rx));
}
__device__ __forceinline__ void split_store2(float x, float y,
                                             __nv_bfloat16* hp, __nv_bfloat16* lp)
{
    uint32_t h, l;
    pack_hilo(x, y, h, l);
    *(uint32_t*)hp = h;
    *(uint32_t*)lp = l;
}

// f32x2 packed multiply: (a,b) *= k
__device__ __forceinline__ void mul2pair(float& a, float& b, uint64_t kk)
{
    uint64_t v, r;
    asm("mov.b64 %0, {%1, %2};" : "=l"(v) : "f"(a), "f"(b));
    asm("mul.rn.f32x2 %0, %1, %2;" : "=l"(r) : "l"(v), "l"(kk));
    asm("mov.b64 {%0, %1}, %2;" : "=f"(a), "=f"(b) : "l"(r));
}
__device__ __forceinline__ uint64_t bcast2(float k)
{
    uint64_t r;
    asm("mov.b64 %0, {%1, %1};" : "=l"(r) : "f"(k));
    return r;
}

// ---------------- fused split kernel (x, W_attn, W_proj in one launch) -----
#define N4_X  2097152
#define N4_WA 786432
#define N4_WP 262144

__global__ __launch_bounds__(256) void split_all_kernel(
    const float4* __restrict__ x,  __nv_bfloat16* __restrict__ xh,  __nv_bfloat16* __restrict__ xl,
    const float4* __restrict__ wa, __nv_bfloat16* __restrict__ wah, __nv_bfloat16* __restrict__ wal,
    const float4* __restrict__ wp, __nv_bfloat16* __restrict__ wph, __nv_bfloat16* __restrict__ wpl)
{
    int i = blockIdx.x * 256 + threadIdx.x;
    const float4* src; __nv_bfloat16 *dh, *dl; int j;
    if (i < N4_X)                 { src = x;  dh = xh;  dl = xl;  j = i; }
    else if (i < N4_X + N4_WA)    { src = wa; dh = wah; dl = wal; j = i - N4_X; }
    else if (i < N4_X + N4_WA + N4_WP) { src = wp; dh = wph; dl = wpl; j = i - N4_X - N4_WA; }
    else return;
    float4 v = src[j];
    split_store2(v.x, v.y, dh + (size_t)j*4,     dl + (size_t)j*4);
    split_store2(v.z, v.w, dh + (size_t)j*4 + 2, dl + (size_t)j*4 + 2);
}

// ---------------------------------------------------------------------------
// mma.sync GEMM on pre-split bf16 (unchanged from R12): C = A * B^T, K=1024.
// ---------------------------------------------------------------------------
#define GROW 144
#define GABUF (128*GROW)            // 18432

template<int BN>
__device__ __forceinline__ void g_load_A(
    uint32_t sbase, int st, int kt, int m0, int tid,
    const __nv_bfloat16* __restrict__ Ah, const __nv_bfloat16* __restrict__ Al)
{
    constexpr int GSTG = 2*GABUF + 2*BN*GROW;
    const int koff = kt * 64;
    const uint32_t dbase = sbase + st * GSTG;
#pragma unroll
    for (int i = 0; i < 4; i++) {
        int gidx = i * 256 + tid;
        int row = gidx >> 3, c = gidx & 7;
        uint32_t doff = row * GROW + c * 16;
        size_t soff = (size_t)(m0 + row) * 1024 + koff + c * 8;
        cp16(dbase + doff,         Ah + soff);
        cp16(dbase + GABUF + doff, Al + soff);
    }
}
template<int BN>
__device__ __forceinline__ void g_load_B(
    uint32_t sbase, int st, int kt, int n0, int tid,
    const __nv_bfloat16* __restrict__ Bh, const __nv_bfloat16* __restrict__ Bl)
{
    constexpr int GSTG = 2*GABUF + 2*BN*GROW;
    constexpr int GBBUF = BN*GROW;
    const int koff = kt * 64;
    const uint32_t dbase = sbase + st * GSTG + 2*GABUF;
#pragma unroll
    for (int i = 0; i < BN/32; i++) {
        int gidx = i * 256 + tid;
        int row = gidx >> 3, c = gidx & 7;
        uint32_t doff = row * GROW + c * 16;
        size_t soff = (size_t)(n0 + row) * 1024 + koff + c * 8;
        cp16(dbase + doff,         Bh + soff);
        cp16(dbase + GBBUF + doff, Bl + soff);
    }
}

template<int BN>
__global__ __launch_bounds__(256, 1) void gemm_mma_kernel(
    const __nv_bfloat16* __restrict__ Ah, const __nv_bfloat16* __restrict__ Al,
    const __nv_bfloat16* __restrict__ Bh, const __nv_bfloat16* __restrict__ Bl,
    __nv_bfloat16* __restrict__ outH, __nv_bfloat16* __restrict__ outL,
    float* __restrict__ outF, const float* __restrict__ bias,
    int ldc, int mode)
{
    constexpr int GBBUF = BN*GROW;
    constexpr int GSTG  = 2*GABUF + 2*GBBUF;
    constexpr int WN    = BN/4;
    constexpr int NCN   = WN/16;
    constexpr int ELD   = BN + 4;

    extern __shared__ char sm[];
    const uint32_t sbase = s2u(sm);
    const int tid  = threadIdx.x;
    const int warp = tid >> 5;
    const int lid  = tid & 31;
    const int g    = lid >> 2;
    const int qr   = lid & 3;
    const int grp  = lid >> 3;
    const int rr   = lid & 7;

    const int m0 = blockIdx.y << 7;
    const int n0 = blockIdx.x * BN;
    const int mw = (warp >> 2) * 64;
    const int nw = (warp & 3) * WN;

    const uint32_t a_rowsel = ((grp & 1) ? 8 : 0) + rr;
    const uint32_t a_colsel = (grp >= 2) ? 16 : 0;
    const uint32_t b_rowsel = ((grp >= 2) ? 8 : 0) + rr;
    const uint32_t b_colsel = (grp & 1) ? 16 : 0;

    float acc[4][2*NCN][4];
#pragma unroll
    for (int mt = 0; mt < 4; mt++)
#pragma unroll
        for (int nt = 0; nt < 2*NCN; nt++) {
            acc[mt][nt][0] = 0.f; acc[mt][nt][1] = 0.f;
            acc[mt][nt][2] = 0.f; acc[mt][nt][3] = 0.f;
        }

    g_load_A<BN>(sbase, 0, 0, m0, tid, Ah, Al);
    g_load_B<BN>(sbase, 0, 0, n0, tid, Bh, Bl);
    cp_commit();

    int stidx = 0;
    for (int kt = 0; kt < 16; kt++) {
        cp_wait0();
        __syncthreads();

        const uint32_t sb  = sbase + stidx * GSTG;
        const uint32_t sAh = sb;
        const uint32_t sAl = sb + GABUF;
        const uint32_t sBh = sb + 2*GABUF;
        const uint32_t sBl = sb + 2*GABUF + GBBUF;

        if (kt + 1 < 16)
            g_load_A<BN>(sbase, stidx ^ 1, kt + 1, m0, tid, Ah, Al);

#pragma unroll
        for (int half = 0; half < 2; half++) {
#pragma unroll
            for (int kq = 0; kq < 2; kq++) {
                const int kk = half*2 + kq;
                uint32_t ah[4][4], al[4][4];
#pragma unroll
                for (int mt = 0; mt < 4; mt++) {
                    uint32_t ra = (mw + mt*16 + a_rowsel) * GROW + kk*32 + a_colsel;
                    ldm4(ah[mt][0], ah[mt][1], ah[mt][2], ah[mt][3], sAh + ra);
                    ldm4(al[mt][0], al[mt][1], al[mt][2], al[mt][3], sAl + ra);
                }
#pragma unroll
                for (int nc = 0; nc < NCN; nc++) {
                    uint32_t rb = (nw + nc*16 + b_rowsel) * GROW + kk*32 + b_colsel;
                    uint32_t bh0, bh1, bh2, bh3, bl0, bl1, bl2, bl3;
                    ldm4(bh0, bh1, bh2, bh3, sBh + rb);
                    ldm4(bl0, bl1, bl2, bl3, sBl + rb);
#pragma unroll
                    for (int mt = 0; mt < 4; mt++) {
                        mma_bf16(acc[mt][2*nc],   ah[mt][0], ah[mt][1], ah[mt][2], ah[mt][3], bh0, bh1);
                        mma_bf16(acc[mt][2*nc+1], ah[mt][0], ah[mt][1], ah[mt][2], ah[mt][3], bh2, bh3);
                    }
#pragma unroll
                    for (int mt = 0; mt < 4; mt++) {
                        mma_bf16(acc[mt][2*nc],   ah[mt][0], ah[mt][1], ah[mt][2], ah[mt][3], bl0, bl1);
                        mma_bf16(acc[mt][2*nc+1], ah[mt][0], ah[mt][1], ah[mt][2], ah[mt][3], bl2, bl3);
                    }
#pragma unroll
                    for (int mt = 0; mt < 4; mt++) {
                        mma_bf16(acc[mt][2*nc],   al[mt][0], al[mt][1], al[mt][2], al[mt][3], bh0, bh1);
                        mma_bf16(acc[mt][2*nc+1], al[mt][0], al[mt][1], al[mt][2], al[mt][3], bh2, bh3);
                    }
                }
            }
            if (half == 0) {
                if (kt + 1 < 16)
                    g_load_B<BN>(sbase, stidx ^ 1, kt + 1, n0, tid, Bh, Bl);
                cp_commit();
            }
        }
        stidx ^= 1;
    }

    __syncthreads();
    float* Sst = (float*)sm;
#pragma unroll
    for (int mt = 0; mt < 4; mt++) {
        int row = mw + mt*16 + g;
#pragma unroll
        for (int nt = 0; nt < 2*NCN; nt++) {
            int col = nw + nt*8 + qr*2;
            *(float2*)&Sst[row*ELD + col]       = make_float2(acc[mt][nt][0], acc[mt][nt][1]);
            *(float2*)&Sst[(row+8)*ELD + col]   = make_float2(acc[mt][nt][2], acc[mt][nt][3]);
        }
    }
    __syncthreads();

    if (mode == 0) {
#pragma unroll 1
        for (int r = 0; r < 16; r++) {
            int row = warp*16 + r;
            size_t ob = (size_t)(m0 + row) * ldc + n0;
#pragma unroll
            for (int blk = 0; blk < BN/64; blk++) {
                int c = blk*64 + lid*2;
                float2 v = *(float2*)&Sst[row*ELD + c];
                split_store2(v.x, v.y, outH + ob + c, outL + ob + c);
            }
        }
    } else {
#pragma unroll 1
        for (int r = 0; r < 16; r++) {
            int row = warp*16 + r;
            size_t ob = (size_t)(m0 + row) * ldc + n0;
#pragma unroll
            for (int blk = 0; blk < BN/128; blk++) {
                int c = blk*128 + lid*4;
                float4 v = *(float4*)&Sst[row*ELD + c];
                v.x += bias[n0 + c];     v.y += bias[n0 + c + 1];
                v.z += bias[n0 + c + 2]; v.w += bias[n0 + c + 3];
                *(float4*)(outF + ob + c) = v;
            }
        }
    }
}

// ---------------------------------------------------------------------------
// Register-resident flash attention. 128 q rows, 8 warps, kv macro-tile 128.
// SOFTWARE-PIPELINED: both subtiles' QK MMAs are issued BEFORE any softmax,
// so the tensor queue drains under the scalar phases. exp2-folded softmax,
// deferred l-reduction, f32x2 rescale, single-cvt packing.
// ---------------------------------------------------------------------------
#define AROW 144
#define AQ_BYTES   (128*AROW)          // 18432
#define AKV_BUF    (128*AROW)          // 18432 per tensor buffer
#define AKV_STAGE  (4*AKV_BUF)         // 73728
#define AKV_OFF    (2*AQ_BYTES)        // 36864
#define ATT_SMEM   (AKV_OFF + 2*AKV_STAGE)   // 184320
#define L2E8 11.541560327111707f       // 8 * log2(e)

__device__ __forceinline__ void attn_cp_kv(
    uint32_t sbase, int st, const __nv_bfloat16* qkvh, const __nv_bfloat16* qkvl,
    size_t rowbase, int tid)
{
    int b = tid >> 6;           // 0:Kh 1:Kl 2:Vh 3:Vl
    int r0 = tid & 63;
    const __nv_bfloat16* base = ((b & 1) ? qkvl : qkvh)
        + rowbase + ((b >> 1) ? 2048 : 1024);
    uint32_t dbuf = sbase + AKV_OFF + st*AKV_STAGE + b*AKV_BUF;
#pragma unroll
    for (int half = 0; half < 2; half++) {
        int row = r0 + half*64;
        const __nv_bfloat16* src = base + (size_t)row * 3072;
        uint32_t dst = dbuf + row*AROW;
#pragma unroll
        for (int c = 0; c < 8; c++) cp16(dst + c*16, src + c*8);
    }
    cp_commit();
}

__global__ __launch_bounds__(256) void attn_fa2_kernel(
    const __nv_bfloat16* __restrict__ qkvh, const __nv_bfloat16* __restrict__ qkvl,
    __nv_bfloat16* __restrict__ atth, __nv_bfloat16* __restrict__ attl)
{
    extern __shared__ char smraw[];
    const uint32_t sbase = s2u(smraw);

    const int tid  = threadIdx.x;
    const int warp = tid >> 5;
    const int lid  = tid & 31;
    const int g    = lid >> 2;
    const int qr   = lid & 3;
    const int grp  = lid >> 3;
    const int rr   = lid & 7;

    const int qt = (gridDim.x - 1) - blockIdx.x;   // longest tiles first
    const int bh = blockIdx.y;
    const int b_ = bh >> 4;
    const int h  = bh & 15;
    const int t0 = qt * 128;

    {
        int qb  = tid >> 7;
        int row = tid & 127;
        const __nv_bfloat16* src = (qb ? qkvl : qkvh)
            + (size_t)(b_*NT + t0 + row) * 3072 + h*HD;
        uint32_t dst = sbase + qb*AQ_BYTES + row*AROW;
#pragma unroll
        for (int c = 0; c < 8; c++) cp16(dst + c*16, src + c*8);
    }
    cp_commit();

    attn_cp_kv(sbase, 0, qkvh, qkvl, (size_t)(b_*NT) * 3072 + h*HD, tid);

    cp_wait1();
    __syncthreads();

    uint32_t aqh[4][4], aql[4][4];
    {
        uint32_t rowoff = (16*warp + ((grp & 1) ? 8 : 0) + rr) * AROW
                        + ((grp >= 2) ? 16 : 0);
#pragma unroll
        for (int kk = 0; kk < 4; kk++) {
            ldm4(aqh[kk][0], aqh[kk][1], aqh[kk][2], aqh[kk][3],
                 sbase + rowoff + kk*32);
            ldm4(aql[kk][0], aql[kk][1], aql[kk][2], aql[kk][3],
                 sbase + AQ_BYTES + rowoff + kk*32);
        }
    }

    float O[8][4];
#pragma unroll
    for (int nt = 0; nt < 8; nt++) {
        O[nt][0] = 0.f; O[nt][1] = 0.f; O[nt][2] = 0.f; O[nt][3] = 0.f;
    }
    float m0 = -1e30f, m1 = -1e30f, l0 = 0.f, l1 = 0.f;

    const int i0 = t0 + 16*warp + g;
    const int i1 = i0 + 8;
    const int njt = qt + 1;               // 128-row macro tiles

    const uint32_t k_rowsel = ((grp >= 2) ? 8 : 0) + rr;
    const uint32_t k_colsel = ((grp & 1) ? 16 : 0);
    const uint32_t v_rowsel = ((grp & 1) ? 8 : 0) + rr;
    const uint32_t v_colsel = ((grp >= 2) ? 16 : 0);

    for (int jt = 0; jt < njt; jt++) {
        const int st = jt & 1;
        if (jt + 1 < njt)
            attn_cp_kv(sbase, st ^ 1, qkvh, qkvl,
                       (size_t)(b_*NT + (jt+1)*128) * 3072 + h*HD, tid);
        if (jt + 1 < njt) cp_wait1(); else cp_wait0();
        __syncthreads();

        const uint32_t sStage = sbase + AKV_OFF + st*AKV_STAGE;
        const bool need_mask = (jt == qt);

        // ---- Phase 1: QK for BOTH subtiles (fills the tensor queue) ----
        float Sall[2][8][4];
#pragma unroll
        for (int sub = 0; sub < 2; sub++) {
            const uint32_t soff = sub * 64 * AROW;
            const uint32_t sKh = sStage + soff;
            const uint32_t sKl = sStage + AKV_BUF + soff;
            float (*S)[4] = Sall[sub];
#pragma unroll
            for (int nt = 0; nt < 8; nt++) {
                S[nt][0] = 0.f; S[nt][1] = 0.f; S[nt][2] = 0.f; S[nt][3] = 0.f;
            }
#pragma unroll
            for (int kk = 0; kk < 4; kk++) {
#pragma unroll
                for (int np = 0; np < 4; np++) {
                    uint32_t addr = (np*16 + k_rowsel)*AROW + kk*32 + k_colsel;
                    uint32_t bh0, bh1, bh2, bh3, bl0, bl1, bl2, bl3;
                    ldm4(bh0, bh1, bh2, bh3, sKh + addr);
                    ldm4(bl0, bl1, bl2, bl3, sKl + addr);
                    mma_bf16(S[2*np],   aqh[kk][0], aqh[kk][1], aqh[kk][2], aqh[kk][3], bh0, bh1);
                    mma_bf16(S[2*np],   aqh[kk][0], aqh[kk][1], aqh[kk][2], aqh[kk][3], bl0, bl1);
                    mma_bf16(S[2*np],   aql[kk][0], aql[kk][1], aql[kk][2], aql[kk][3], bh0, bh1);
                    mma_bf16(S[2*np+1], aqh[kk][0], aqh[kk][1], aqh[kk][2], aqh[kk][3], bh2, bh3);
                    mma_bf16(S[2*np+1], aqh[kk][0], aqh[kk][1], aqh[kk][2], aqh[kk][3], bl2, bl3);
                    mma_bf16(S[2*np+1], aql[kk][0], aql[kk][1], aql[kk][2], aql[kk][3], bh2, bh3);
                }
            }
        }

        // ---- Phase 2: per-sub softmax + PV (softmax overlaps queue drain) --
#pragma unroll
        for (int sub = 0; sub < 2; sub++) {
            const uint32_t soff = sub * 64 * AROW;
            const uint32_t sVh = sStage + 2*AKV_BUF + soff;
            const uint32_t sVl = sStage + 3*AKV_BUF + soff;
            float (*S)[4] = Sall[sub];

            if (need_mask) {
                const int jbase = jt*128 + sub*64;
#pragma unroll
                for (int nt = 0; nt < 8; nt++) {
                    int jb = jbase + nt*8 + qr*2;
                    if (jb     > i0) S[nt][0] = -1e30f;
                    if (jb + 1 > i0) S[nt][1] = -1e30f;
                    if (jb     > i1) S[nt][2] = -1e30f;
                    if (jb + 1 > i1) S[nt][3] = -1e30f;
                }
            }

            float mx0 = -1e30f, mx1 = -1e30f;
#pragma unroll
            for (int nt = 0; nt < 8; nt++) {
                mx0 = fmaxf(mx0, fmaxf(S[nt][0], S[nt][1]));
                mx1 = fmaxf(mx1, fmaxf(S[nt][2], S[nt][3]));
            }
            mx0 = fmaxf(mx0, __shfl_xor_sync(0xffffffffu, mx0, 1));
            mx0 = fmaxf(mx0, __shfl_xor_sync(0xffffffffu, mx0, 2));
            mx1 = fmaxf(mx1, __shfl_xor_sync(0xffffffffu, mx1, 1));
            mx1 = fmaxf(mx1, __shfl_xor_sync(0xffffffffu, mx1, 2));

            float mn0 = fmaxf(m0, mx0), mn1 = fmaxf(m1, mx1);
            float corr0 = exp2f((m0 - mn0) * L2E8);
            float corr1 = exp2f((m1 - mn1) * L2E8);
            m0 = mn0; m1 = mn1;
            const float c0 = mn0 * L2E8;
            const float c1 = mn1 * L2E8;

            float sum0 = 0.f, sum1 = 0.f;
#pragma unroll
            for (int nt = 0; nt < 8; nt++) {
                float p0 = exp2f(fmaf(S[nt][0], L2E8, -c0));
                float p1 = exp2f(fmaf(S[nt][1], L2E8, -c0));
                float p2 = exp2f(fmaf(S[nt][2], L2E8, -c1));
                float p3 = exp2f(fmaf(S[nt][3], L2E8, -c1));
                sum0 += p0 + p1; sum1 += p2 + p3;
                S[nt][0] = p0; S[nt][1] = p1; S[nt][2] = p2; S[nt][3] = p3;
            }
            l0 = l0 * corr0 + sum0;
            l1 = l1 * corr1 + sum1;

            {
                uint64_t cc0 = bcast2(corr0), cc1 = bcast2(corr1);
#pragma unroll
                for (int nt = 0; nt < 8; nt++) {
                    mul2pair(O[nt][0], O[nt][1], cc0);
                    mul2pair(O[nt][2], O[nt][3], cc1);
                }
            }

#pragma unroll
            for (int kk = 0; kk < 4; kk++) {
                uint32_t ah0, ah1, ah2, ah3, al0, al1, al2, al3;
                pack_hilo(S[2*kk][0],   S[2*kk][1],   ah0, al0);
                pack_hilo(S[2*kk][2],   S[2*kk][3],   ah1, al1);
                pack_hilo(S[2*kk+1][0], S[2*kk+1][1], ah2, al2);
                pack_hilo(S[2*kk+1][2], S[2*kk+1][3], ah3, al3);
#pragma unroll
                for (int np = 0; np < 4; np++) {
                    uint32_t addr = (kk*16 + v_rowsel)*AROW + np*32 + v_colsel;
                    uint32_t bh0, bh1, bh2, bh3, bl0, bl1, bl2, bl3;
                    ldm4t(bh0, bh1, bh2, bh3, sVh + addr);
                    ldm4t(bl0, bl1, bl2, bl3, sVl + addr);
                    mma_bf16(O[2*np],   ah0, ah1, ah2, ah3, bh0, bh1);
                    mma_bf16(O[2*np],   ah0, ah1, ah2, ah3, bl0, bl1);
                    mma_bf16(O[2*np],   al0, al1, al2, al3, bh0, bh1);
                    mma_bf16(O[2*np+1], ah0, ah1, ah2, ah3, bh2, bh3);
                    mma_bf16(O[2*np+1], ah0, ah1, ah2, ah3, bl2, bl3);
                    mma_bf16(O[2*np+1], al0, al1, al2, al3, bh2, bh3);
                }
            }
        }
        __syncthreads();
    }

    // final quad reduction of partial l, then normalize + store
    l0 += __shfl_xor_sync(0xffffffffu, l0, 1);
    l0 += __shfl_xor_sync(0xffffffffu, l0, 2);
    l1 += __shfl_xor_sync(0xffffffffu, l1, 1);
    l1 += __shfl_xor_sync(0xffffffffu, l1, 2);

    float inv0 = 1.f / l0, inv1 = 1.f / l1;
    size_t r0 = (size_t)(b_*NT + i0) * NC + h*HD + qr*2;
    size_t r1 = (size_t)(b_*NT + i1) * NC + h*HD + qr*2;
#pragma unroll
    for (int nt = 0; nt < 8; nt++) {
        split_store2(O[nt][0]*inv0, O[nt][1]*inv0, atth + r0 + nt*8, attl + r0 + nt*8);
        split_store2(O[nt][2]*inv1, O[nt][3]*inv1, atth + r1 + nt*8, attl + r1 + nt*8);
    }
}

// ---------------------------------------------------------------------------

extern "C" void kernel_launch(void* const* d_in, const int* in_sizes, int n_in,
                              void* d_out, int out_size)
{
    const float* x      = (const float*)d_in[0];
    const float* W_attn = (const float*)d_in[1];
    const float* W_proj = (const float*)d_in[2];
    const float* b_proj = (const float*)d_in[3];
    float* out = (float*)d_out;

    __nv_bfloat16 *xh, *xl, *wah, *wal, *wph, *wpl, *qkvh, *qkvl, *atth, *attl;
    cudaGetSymbolAddress((void**)&xh,   g_xh);
    cudaGetSymbolAddress((void**)&xl,   g_xl);
    cudaGetSymbolAddress((void**)&wah,  g_wah);
    cudaGetSymbolAddress((void**)&wal,  g_wal);
    cudaGetSymbolAddress((void**)&wph,  g_wph);
    cudaGetSymbolAddress((void**)&wpl,  g_wpl);
    cudaGetSymbolAddress((void**)&qkvh, g_qkvh);
    cudaGetSymbolAddress((void**)&qkvl, g_qkvl);
    cudaGetSymbolAddress((void**)&atth, g_atth);
    cudaGetSymbolAddress((void**)&attl, g_attl);

    constexpr int SM192 = 2*(2*GABUF + 2*192*GROW);   // 184320
    constexpr int SM256 = 2*(2*GABUF + 2*256*GROW);   // 221184

    cudaFuncSetAttribute(gemm_mma_kernel<192>,
                         cudaFuncAttributeMaxDynamicSharedMemorySize, SM192);
    cudaFuncSetAttribute(gemm_mma_kernel<256>,
                         cudaFuncAttributeMaxDynamicSharedMemorySize, SM256);
    cudaFuncSetAttribute(attn_fa2_kernel,
                         cudaFuncAttributeMaxDynamicSharedMemorySize, ATT_SMEM);

    // fused pre-split of x, W_attn, W_proj
    split_all_kernel<<<(N4_X + N4_WA + N4_WP + 255) / 256, 256>>>(
        (const float4*)x, xh, xl,
        (const float4*)W_attn, wah, wal,
        (const float4*)W_proj, wph, wpl);

    // QKV: BN=192, 1024 CTAs (wave-quantization friendly)
    gemm_mma_kernel<192><<<dim3(16, 64), 256, SM192>>>(
        xh, xl, wah, wal, qkvh, qkvl, nullptr, nullptr, 3072, 0);

    // attention: 128-row q tiles, kv macro 128, pipelined QK/softmax
    attn_fa2_kernel<<<dim3(16, 64), 256, ATT_SMEM>>>(qkvh, qkvl, atth, attl);

    // proj: BN=256 + bias -> f32 out
    gemm_mma_kernel<256><<<dim3(4, 64), 256, SM256>>>(
        atth, attl, wph, wpl, nullptr, nullptr, out, b_proj, 1024, 1);
}

// round 15
// speedup vs baseline: 1.0689x; 1.0007x over previous
#include <cuda_runtime.h>
#include <cuda_bf16.h>
#include <math.h>
#include <cstdint>

#define NB 4
#define NT 2048
#define NC 1024
#define NH 16
#define HD 64
#define MM (NB*NT)          // 8192

// ---------------- global scratch (device globals; no runtime alloc) --------
__device__ __nv_bfloat16 g_xh[(size_t)MM*NC],    g_xl[(size_t)MM*NC];
__device__ __nv_bfloat16 g_wah[(size_t)3*NC*NC], g_wal[(size_t)3*NC*NC];
__device__ __nv_bfloat16 g_wph[(size_t)NC*NC],   g_wpl[(size_t)NC*NC];
__device__ __nv_bfloat16 g_qkvh[(size_t)MM*3*NC],g_qkvl[(size_t)MM*3*NC];
__device__ __nv_bfloat16 g_atth[(size_t)MM*NC],  g_attl[(size_t)MM*NC];

// ---------------- helpers --------------------------------------------------
__device__ __forceinline__ uint32_t s2u(const void* p) {
    return (uint32_t)__cvta_generic_to_shared(p);
}
__device__ __forceinline__ void cp16(uint32_t dst, const void* src) {
    asm volatile("cp.async.cg.shared.global [%0], [%1], 16;" :: "r"(dst), "l"(src));
}
__device__ __forceinline__ void cp_commit() {
    asm volatile("cp.async.commit_group;" ::: "memory");
}
__device__ __forceinline__ void cp_wait1() {
    asm volatile("cp.async.wait_group 1;" ::: "memory");
}
__device__ __forceinline__ void cp_wait0() {
    asm volatile("cp.async.wait_group 0;" ::: "memory");
}
__device__ __forceinline__ void ldm4(uint32_t& r0, uint32_t& r1, uint32_t& r2,
                                     uint32_t& r3, uint32_t a) {
    asm volatile("ldmatrix.sync.aligned.m8n8.x4.shared.b16 {%0,%1,%2,%3}, [%4];"
                 : "=r"(r0), "=r"(r1), "=r"(r2), "=r"(r3) : "r"(a));
}
__device__ __forceinline__ void ldm4t(uint32_t& r0, uint32_t& r1, uint32_t& r2,
                                      uint32_t& r3, uint32_t a) {
    asm volatile("ldmatrix.sync.aligned.m8n8.x4.trans.shared.b16 {%0,%1,%2,%3}, [%4];"
                 : "=r"(r0), "=r"(r1), "=r"(r2), "=r"(r3) : "r"(a));
}
__device__ __forceinline__ void mma_bf16(float* c, uint32_t a0, uint32_t a1,
                                         uint32_t a2, uint32_t a3,
                                         uint32_t b0, uint32_t b1) {
    asm volatile("mma.sync.aligned.m16n8k16.row.col.f32.bf16.bf16.f32 "
                 "{%0,%1,%2,%3}, {%4,%5,%6,%7}, {%8,%9}, {%0,%1,%2,%3};"
                 : "+f"(c[0]), "+f"(c[1]), "+f"(c[2]), "+f"(c[3])
                 : "r"(a0), "r"(a1), "r"(a2), "r"(a3), "r"(b0), "r"(b1));
}

// Fast split: one cvt.rn.bf16x2 per pair; residual via integer shifts.
__device__ __forceinline__ void pack_hilo(float x, float y, uint32_t& h, uint32_t& l)
{
    asm("cvt.rn.bf16x2.f32 %0, %1, %2;" : "=r"(h) : "f"(y), "f"(x));
    float hx = __uint_as_float(h << 16);
    float hy = __uint_as_float(h & 0xFFFF0000u);
    float rx = x - hx;
    float ry = y - hy;
    asm("cvt.rn.bf16x2.f32 %0, %1, %2;" : "=r"(l) : "f"(ry), "f"(rx));
}
__device__ __forceinline__ void split_store2(float x, float y,
                                             __nv_bfloat16* hp, __nv_bfloat16* lp)
{
    uint32_t h, l;
    pack_hilo(x, y, h, l);
    *(uint32_t*)hp = h;
    *(uint32_t*)lp = l;
}

// f32x2 packed multiply: (a,b) *= k
__device__ __forceinline__ void mul2pair(float& a, float& b, uint64_t kk)
{
    uint64_t v, r;
    asm("mov.b64 %0, {%1, %2};" : "=l"(v) : "f"(a), "f"(b));
    asm("mul.rn.f32x2 %0, %1, %2;" : "=l"(r) : "l"(v), "l"(kk));
    asm("mov.b64 {%0, %1}, %2;" : "=f"(a), "=f"(b) : "l"(r));
}
__device__ __forceinline__ uint64_t bcast2(float k)
{
    uint64_t r;
    asm("mov.b64 %0, {%1, %1};" : "=l"(r) : "f"(k));
    return r;
}

// ---------------- fused split kernel (x, W_attn, W_proj in one launch) -----
#define N4_X  2097152
#define N4_WA 786432
#define N4_WP 262144

__global__ __launch_bounds__(256) void split_all_kernel(
    const float4* __restrict__ x,  __nv_bfloat16* __restrict__ xh,  __nv_bfloat16* __restrict__ xl,
    const float4* __restrict__ wa, __nv_bfloat16* __restrict__ wah, __nv_bfloat16* __restrict__ wal,
    const float4* __restrict__ wp, __nv_bfloat16* __restrict__ wph, __nv_bfloat16* __restrict__ wpl)
{
    int i = blockIdx.x * 256 + threadIdx.x;
    const float4* src; __nv_bfloat16 *dh, *dl; int j;
    if (i < N4_X)                 { src = x;  dh = xh;  dl = xl;  j = i; }
    else if (i < N4_X + N4_WA)    { src = wa; dh = wah; dl = wal; j = i - N4_X; }
    else if (i < N4_X + N4_WA + N4_WP) { src = wp; dh = wph; dl = wpl; j = i - N4_X - N4_WA; }
    else return;
    float4 v = src[j];
    split_store2(v.x, v.y, dh + (size_t)j*4,     dl + (size_t)j*4);
    split_store2(v.z, v.w, dh + (size_t)j*4 + 2, dl + (size_t)j*4 + 2);
}

// ---------------------------------------------------------------------------
// mma.sync GEMM on pre-split bf16 (frozen R12 winner): C = A * B^T, K=1024.
// ---------------------------------------------------------------------------
#define GROW 144
#define GABUF (128*GROW)            // 18432

template<int BN>
__device__ __forceinline__ void g_load_A(
    uint32_t sbase, int st, int kt, int m0, int tid,
    const __nv_bfloat16* __restrict__ Ah, const __nv_bfloat16* __restrict__ Al)
{
    constexpr int GSTG = 2*GABUF + 2*BN*GROW;
    const int koff = kt * 64;
    const uint32_t dbase = sbase + st * GSTG;
#pragma unroll
    for (int i = 0; i < 4; i++) {
        int gidx = i * 256 + tid;
        int row = gidx >> 3, c = gidx & 7;
        uint32_t doff = row * GROW + c * 16;
        size_t soff = (size_t)(m0 + row) * 1024 + koff + c * 8;
        cp16(dbase + doff,         Ah + soff);
        cp16(dbase + GABUF + doff, Al + soff);
    }
}
template<int BN>
__device__ __forceinline__ void g_load_B(
    uint32_t sbase, int st, int kt, int n0, int tid,
    const __nv_bfloat16* __restrict__ Bh, const __nv_bfloat16* __restrict__ Bl)
{
    constexpr int GSTG = 2*GABUF + 2*BN*GROW;
    constexpr int GBBUF = BN*GROW;
    const int koff = kt * 64;
    const uint32_t dbase = sbase + st * GSTG + 2*GABUF;
#pragma unroll
    for (int i = 0; i < BN/32; i++) {
        int gidx = i * 256 + tid;
        int row = gidx >> 3, c = gidx & 7;
        uint32_t doff = row * GROW + c * 16;
        size_t soff = (size_t)(n0 + row) * 1024 + koff + c * 8;
        cp16(dbase + doff,         Bh + soff);
        cp16(dbase + GBBUF + doff, Bl + soff);
    }
}

template<int BN>
__global__ __launch_bounds__(256, 1) void gemm_mma_kernel(
    const __nv_bfloat16* __restrict__ Ah, const __nv_bfloat16* __restrict__ Al,
    const __nv_bfloat16* __restrict__ Bh, const __nv_bfloat16* __restrict__ Bl,
    __nv_bfloat16* __restrict__ outH, __nv_bfloat16* __restrict__ outL,
    float* __restrict__ outF, const float* __restrict__ bias,
    int ldc, int mode)
{
    constexpr int GBBUF = BN*GROW;
    constexpr int GSTG  = 2*GABUF + 2*GBBUF;
    constexpr int WN    = BN/4;
    constexpr int NCN   = WN/16;
    constexpr int ELD   = BN + 4;

    extern __shared__ char sm[];
    const uint32_t sbase = s2u(sm);
    const int tid  = threadIdx.x;
    const int warp = tid >> 5;
    const int lid  = tid & 31;
    const int g    = lid >> 2;
    const int qr   = lid & 3;
    const int grp  = lid >> 3;
    const int rr   = lid & 7;

    const int m0 = blockIdx.y << 7;
    const int n0 = blockIdx.x * BN;
    const int mw = (warp >> 2) * 64;
    const int nw = (warp & 3) * WN;

    const uint32_t a_rowsel = ((grp & 1) ? 8 : 0) + rr;
    const uint32_t a_colsel = (grp >= 2) ? 16 : 0;
    const uint32_t b_rowsel = ((grp >= 2) ? 8 : 0) + rr;
    const uint32_t b_colsel = (grp & 1) ? 16 : 0;

    float acc[4][2*NCN][4];
#pragma unroll
    for (int mt = 0; mt < 4; mt++)
#pragma unroll
        for (int nt = 0; nt < 2*NCN; nt++) {
            acc[mt][nt][0] = 0.f; acc[mt][nt][1] = 0.f;
            acc[mt][nt][2] = 0.f; acc[mt][nt][3] = 0.f;
        }

    g_load_A<BN>(sbase, 0, 0, m0, tid, Ah, Al);
    g_load_B<BN>(sbase, 0, 0, n0, tid, Bh, Bl);
    cp_commit();

    int stidx = 0;
    for (int kt = 0; kt < 16; kt++) {
        cp_wait0();
        __syncthreads();

        const uint32_t sb  = sbase + stidx * GSTG;
        const uint32_t sAh = sb;
        const uint32_t sAl = sb + GABUF;
        const uint32_t sBh = sb + 2*GABUF;
        const uint32_t sBl = sb + 2*GABUF + GBBUF;

        if (kt + 1 < 16)
            g_load_A<BN>(sbase, stidx ^ 1, kt + 1, m0, tid, Ah, Al);

#pragma unroll
        for (int half = 0; half < 2; half++) {
#pragma unroll
            for (int kq = 0; kq < 2; kq++) {
                const int kk = half*2 + kq;
                uint32_t ah[4][4], al[4][4];
#pragma unroll
                for (int mt = 0; mt < 4; mt++) {
                    uint32_t ra = (mw + mt*16 + a_rowsel) * GROW + kk*32 + a_colsel;
                    ldm4(ah[mt][0], ah[mt][1], ah[mt][2], ah[mt][3], sAh + ra);
                    ldm4(al[mt][0], al[mt][1], al[mt][2], al[mt][3], sAl + ra);
                }
#pragma unroll
                for (int nc = 0; nc < NCN; nc++) {
                    uint32_t rb = (nw + nc*16 + b_rowsel) * GROW + kk*32 + b_colsel;
                    uint32_t bh0, bh1, bh2, bh3, bl0, bl1, bl2, bl3;
                    ldm4(bh0, bh1, bh2, bh3, sBh + rb);
                    ldm4(bl0, bl1, bl2, bl3, sBl + rb);
#pragma unroll
                    for (int mt = 0; mt < 4; mt++) {
                        mma_bf16(acc[mt][2*nc],   ah[mt][0], ah[mt][1], ah[mt][2], ah[mt][3], bh0, bh1);
                        mma_bf16(acc[mt][2*nc+1], ah[mt][0], ah[mt][1], ah[mt][2], ah[mt][3], bh2, bh3);
                    }
#pragma unroll
                    for (int mt = 0; mt < 4; mt++) {
                        mma_bf16(acc[mt][2*nc],   ah[mt][0], ah[mt][1], ah[mt][2], ah[mt][3], bl0, bl1);
                        mma_bf16(acc[mt][2*nc+1], ah[mt][0], ah[mt][1], ah[mt][2], ah[mt][3], bl2, bl3);
                    }
#pragma unroll
                    for (int mt = 0; mt < 4; mt++) {
                        mma_bf16(acc[mt][2*nc],   al[mt][0], al[mt][1], al[mt][2], al[mt][3], bh0, bh1);
                        mma_bf16(acc[mt][2*nc+1], al[mt][0], al[mt][1], al[mt][2], al[mt][3], bh2, bh3);
                    }
                }
            }
            if (half == 0) {
                if (kt + 1 < 16)
                    g_load_B<BN>(sbase, stidx ^ 1, kt + 1, n0, tid, Bh, Bl);
                cp_commit();
            }
        }
        stidx ^= 1;
    }

    __syncthreads();
    float* Sst = (float*)sm;
#pragma unroll
    for (int mt = 0; mt < 4; mt++) {
        int row = mw + mt*16 + g;
#pragma unroll
        for (int nt = 0; nt < 2*NCN; nt++) {
            int col = nw + nt*8 + qr*2;
            *(float2*)&Sst[row*ELD + col]       = make_float2(acc[mt][nt][0], acc[mt][nt][1]);
            *(float2*)&Sst[(row+8)*ELD + col]   = make_float2(acc[mt][nt][2], acc[mt][nt][3]);
        }
    }
    __syncthreads();

    if (mode == 0) {
#pragma unroll 1
        for (int r = 0; r < 16; r++) {
            int row = warp*16 + r;
            size_t ob = (size_t)(m0 + row) * ldc + n0;
#pragma unroll
            for (int blk = 0; blk < BN/64; blk++) {
                int c = blk*64 + lid*2;
                float2 v = *(float2*)&Sst[row*ELD + c];
                split_store2(v.x, v.y, outH + ob + c, outL + ob + c);
            }
        }
    } else {
#pragma unroll 1
        for (int r = 0; r < 16; r++) {
            int row = warp*16 + r;
            size_t ob = (size_t)(m0 + row) * ldc + n0;
#pragma unroll
            for (int blk = 0; blk < BN/128; blk++) {
                int c = blk*128 + lid*4;
                float4 v = *(float4*)&Sst[row*ELD + c];
                v.x += bias[n0 + c];     v.y += bias[n0 + c + 1];
                v.z += bias[n0 + c + 2]; v.w += bias[n0 + c + 3];
                *(float4*)(outF + ob + c) = v;
            }
        }
    }
}

// ---------------------------------------------------------------------------
// Register-resident flash attention. 128 q rows, 8 warps, kv macro-tile 128.
// Phase-1 computes S for the WHOLE macro tile; softmax statistics (max, corr,
// O-rescale, shuffles) are computed ONCE per 128 kv rows instead of per 64.
// exp2-folded softmax, deferred l-reduction, f32x2 rescale, fast packing.
// ---------------------------------------------------------------------------
#define AROW 144
#define AQ_BYTES   (128*AROW)          // 18432
#define AKV_BUF    (128*AROW)          // 18432 per tensor buffer
#define AKV_STAGE  (4*AKV_BUF)         // 73728
#define AKV_OFF    (2*AQ_BYTES)        // 36864
#define ATT_SMEM   (AKV_OFF + 2*AKV_STAGE)   // 184320
#define L2E8 11.541560327111707f       // 8 * log2(e)

__device__ __forceinline__ void attn_cp_kv(
    uint32_t sbase, int st, const __nv_bfloat16* qkvh, const __nv_bfloat16* qkvl,
    size_t rowbase, int tid)
{
    int b = tid >> 6;           // 0:Kh 1:Kl 2:Vh 3:Vl
    int r0 = tid & 63;
    const __nv_bfloat16* base = ((b & 1) ? qkvl : qkvh)
        + rowbase + ((b >> 1) ? 2048 : 1024);
    uint32_t dbuf = sbase + AKV_OFF + st*AKV_STAGE + b*AKV_BUF;
#pragma unroll
    for (int half = 0; half < 2; half++) {
        int row = r0 + half*64;
        const __nv_bfloat16* src = base + (size_t)row * 3072;
        uint32_t dst = dbuf + row*AROW;
#pragma unroll
        for (int c = 0; c < 8; c++) cp16(dst + c*16, src + c*8);
    }
    cp_commit();
}

__global__ __launch_bounds__(256) void attn_fa2_kernel(
    const __nv_bfloat16* __restrict__ qkvh, const __nv_bfloat16* __restrict__ qkvl,
    __nv_bfloat16* __restrict__ atth, __nv_bfloat16* __restrict__ attl)
{
    extern __shared__ char smraw[];
    const uint32_t sbase = s2u(smraw);

    const int tid  = threadIdx.x;
    const int warp = tid >> 5;
    const int lid  = tid & 31;
    const int g    = lid >> 2;
    const int qr   = lid & 3;
    const int grp  = lid >> 3;
    const int rr   = lid & 7;

    const int qt = (gridDim.x - 1) - blockIdx.x;   // longest tiles first
    const int bh = blockIdx.y;
    const int b_ = bh >> 4;
    const int h  = bh & 15;
    const int t0 = qt * 128;

    {
        int qb  = tid >> 7;
        int row = tid & 127;
        const __nv_bfloat16* src = (qb ? qkvl : qkvh)
            + (size_t)(b_*NT + t0 + row) * 3072 + h*HD;
        uint32_t dst = sbase + qb*AQ_BYTES + row*AROW;
#pragma unroll
        for (int c = 0; c < 8; c++) cp16(dst + c*16, src + c*8);
    }
    cp_commit();

    attn_cp_kv(sbase, 0, qkvh, qkvl, (size_t)(b_*NT) * 3072 + h*HD, tid);

    cp_wait1();
    __syncthreads();

    uint32_t aqh[4][4], aql[4][4];
    {
        uint32_t rowoff = (16*warp + ((grp & 1) ? 8 : 0) + rr) * AROW
                        + ((grp >= 2) ? 16 : 0);
#pragma unroll
        for (int kk = 0; kk < 4; kk++) {
            ldm4(aqh[kk][0], aqh[kk][1], aqh[kk][2], aqh[kk][3],
                 sbase + rowoff + kk*32);
            ldm4(aql[kk][0], aql[kk][1], aql[kk][2], aql[kk][3],
                 sbase + AQ_BYTES + rowoff + kk*32);
        }
    }

    float O[8][4];
#pragma unroll
    for (int nt = 0; nt < 8; nt++) {
        O[nt][0] = 0.f; O[nt][1] = 0.f; O[nt][2] = 0.f; O[nt][3] = 0.f;
    }
    float m0 = -1e30f, m1 = -1e30f, l0 = 0.f, l1 = 0.f;

    const int i0 = t0 + 16*warp + g;
    const int i1 = i0 + 8;
    const int njt = qt + 1;               // 128-row macro tiles

    const uint32_t k_rowsel = ((grp >= 2) ? 8 : 0) + rr;
    const uint32_t k_colsel = ((grp & 1) ? 16 : 0);
    const uint32_t v_rowsel = ((grp & 1) ? 8 : 0) + rr;
    const uint32_t v_colsel = ((grp >= 2) ? 16 : 0);

    for (int jt = 0; jt < njt; jt++) {
        const int st = jt & 1;
        if (jt + 1 < njt)
            attn_cp_kv(sbase, st ^ 1, qkvh, qkvl,
                       (size_t)(b_*NT + (jt+1)*128) * 3072 + h*HD, tid);
        if (jt + 1 < njt) cp_wait1(); else cp_wait0();
        __syncthreads();

        const uint32_t sStage = sbase + AKV_OFF + st*AKV_STAGE;
        const bool need_mask = (jt == qt);

        // ---- Phase 1: QK for BOTH subtiles ----
        float Sall[2][8][4];
#pragma unroll
        for (int sub = 0; sub < 2; sub++) {
            const uint32_t soff = sub * 64 * AROW;
            const uint32_t sKh = sStage + soff;
            const uint32_t sKl = sStage + AKV_BUF + soff;
            float (*S)[4] = Sall[sub];
#pragma unroll
            for (int nt = 0; nt < 8; nt++) {
                S[nt][0] = 0.f; S[nt][1] = 0.f; S[nt][2] = 0.f; S[nt][3] = 0.f;
            }
#pragma unroll
            for (int kk = 0; kk < 4; kk++) {
#pragma unroll
                for (int np = 0; np < 4; np++) {
                    uint32_t addr = (np*16 + k_rowsel)*AROW + kk*32 + k_colsel;
                    uint32_t bh0, bh1, bh2, bh3, bl0, bl1, bl2, bl3;
                    ldm4(bh0, bh1, bh2, bh3, sKh + addr);
                    ldm4(bl0, bl1, bl2, bl3, sKl + addr);
                    mma_bf16(S[2*np],   aqh[kk][0], aqh[kk][1], aqh[kk][2], aqh[kk][3], bh0, bh1);
                    mma_bf16(S[2*np],   aqh[kk][0], aqh[kk][1], aqh[kk][2], aqh[kk][3], bl0, bl1);
                    mma_bf16(S[2*np],   aql[kk][0], aql[kk][1], aql[kk][2], aql[kk][3], bh0, bh1);
                    mma_bf16(S[2*np+1], aqh[kk][0], aqh[kk][1], aqh[kk][2], aqh[kk][3], bh2, bh3);
                    mma_bf16(S[2*np+1], aqh[kk][0], aqh[kk][1], aqh[kk][2], aqh[kk][3], bl2, bl3);
                    mma_bf16(S[2*np+1], aql[kk][0], aql[kk][1], aql[kk][2], aql[kk][3], bh2, bh3);
                }
            }
        }

        // ---- Phase 2a: mask (raw logit domain) ----
        if (need_mask) {
#pragma unroll
            for (int sub = 0; sub < 2; sub++) {
                float (*S)[4] = Sall[sub];
                const int jbase = jt*128 + sub*64;
#pragma unroll
                for (int nt = 0; nt < 8; nt++) {
                    int jb = jbase + nt*8 + qr*2;
                    if (jb     > i0) S[nt][0] = -1e30f;
                    if (jb + 1 > i0) S[nt][1] = -1e30f;
                    if (jb     > i1) S[nt][2] = -1e30f;
                    if (jb + 1 > i1) S[nt][3] = -1e30f;
                }
            }
        }

        // ---- Phase 2b: SINGLE max / corr / O-rescale over the macro tile --
        float mx0 = -1e30f, mx1 = -1e30f;
#pragma unroll
        for (int sub = 0; sub < 2; sub++) {
            float (*S)[4] = Sall[sub];
#pragma unroll
            for (int nt = 0; nt < 8; nt++) {
                mx0 = fmaxf(mx0, fmaxf(S[nt][0], S[nt][1]));
                mx1 = fmaxf(mx1, fmaxf(S[nt][2], S[nt][3]));
            }
        }
        mx0 = fmaxf(mx0, __shfl_xor_sync(0xffffffffu, mx0, 1));
        mx0 = fmaxf(mx0, __shfl_xor_sync(0xffffffffu, mx0, 2));
        mx1 = fmaxf(mx1, __shfl_xor_sync(0xffffffffu, mx1, 1));
        mx1 = fmaxf(mx1, __shfl_xor_sync(0xffffffffu, mx1, 2));

        float mn0 = fmaxf(m0, mx0), mn1 = fmaxf(m1, mx1);
        float corr0 = exp2f((m0 - mn0) * L2E8);
        float corr1 = exp2f((m1 - mn1) * L2E8);
        m0 = mn0; m1 = mn1;
        const float c0 = mn0 * L2E8;
        const float c1 = mn1 * L2E8;

        {
            uint64_t cc0 = bcast2(corr0), cc1 = bcast2(corr1);
#pragma unroll
            for (int nt = 0; nt < 8; nt++) {
                mul2pair(O[nt][0], O[nt][1], cc0);
                mul2pair(O[nt][2], O[nt][3], cc1);
            }
        }
        l0 *= corr0;
        l1 *= corr1;

        // ---- Phase 2c+d: per-sub exp + pack + PV ----
#pragma unroll
        for (int sub = 0; sub < 2; sub++) {
            const uint32_t soff = sub * 64 * AROW;
            const uint32_t sVh = sStage + 2*AKV_BUF + soff;
            const uint32_t sVl = sStage + 3*AKV_BUF + soff;
            float (*S)[4] = Sall[sub];

            float sum0 = 0.f, sum1 = 0.f;
#pragma unroll
            for (int nt = 0; nt < 8; nt++) {
                float p0 = exp2f(fmaf(S[nt][0], L2E8, -c0));
                float p1 = exp2f(fmaf(S[nt][1], L2E8, -c0));
                float p2 = exp2f(fmaf(S[nt][2], L2E8, -c1));
                float p3 = exp2f(fmaf(S[nt][3], L2E8, -c1));
                sum0 += p0 + p1; sum1 += p2 + p3;
                S[nt][0] = p0; S[nt][1] = p1; S[nt][2] = p2; S[nt][3] = p3;
            }
            l0 += sum0;
            l1 += sum1;

#pragma unroll
            for (int kk = 0; kk < 4; kk++) {
                uint32_t ah0, ah1, ah2, ah3, al0, al1, al2, al3;
                pack_hilo(S[2*kk][0],   S[2*kk][1],   ah0, al0);
                pack_hilo(S[2*kk][2],   S[2*kk][3],   ah1, al1);
                pack_hilo(S[2*kk+1][0], S[2*kk+1][1], ah2, al2);
                pack_hilo(S[2*kk+1][2], S[2*kk+1][3], ah3, al3);
#pragma unroll
                for (int np = 0; np < 4; np++) {
                    uint32_t addr = (kk*16 + v_rowsel)*AROW + np*32 + v_colsel;
                    uint32_t bh0, bh1, bh2, bh3, bl0, bl1, bl2, bl3;
                    ldm4t(bh0, bh1, bh2, bh3, sVh + addr);
                    ldm4t(bl0, bl1, bl2, bl3, sVl + addr);
                    mma_bf16(O[2*np],   ah0, ah1, ah2, ah3, bh0, bh1);
                    mma_bf16(O[2*np],   ah0, ah1, ah2, ah3, bl0, bl1);
                    mma_bf16(O[2*np],   al0, al1, al2, al3, bh0, bh1);
                    mma_bf16(O[2*np+1], ah0, ah1, ah2, ah3, bh2, bh3);
                    mma_bf16(O[2*np+1], ah0, ah1, ah2, ah3, bl2, bl3);
                    mma_bf16(O[2*np+1], al0, al1, al2, al3, bh2, bh3);
                }
            }
        }
        __syncthreads();
    }

    // final quad reduction of partial l, then normalize + store
    l0 += __shfl_xor_sync(0xffffffffu, l0, 1);
    l0 += __shfl_xor_sync(0xffffffffu, l0, 2);
    l1 += __shfl_xor_sync(0xffffffffu, l1, 1);
    l1 += __shfl_xor_sync(0xffffffffu, l1, 2);

    float inv0 = 1.f / l0, inv1 = 1.f / l1;
    size_t r0 = (size_t)(b_*NT + i0) * NC + h*HD + qr*2;
    size_t r1 = (size_t)(b_*NT + i1) * NC + h*HD + qr*2;
#pragma unroll
    for (int nt = 0; nt < 8; nt++) {
        split_store2(O[nt][0]*inv0, O[nt][1]*inv0, atth + r0 + nt*8, attl + r0 + nt*8);
        split_store2(O[nt][2]*inv1, O[nt][3]*inv1, atth + r1 + nt*8, attl + r1 + nt*8);
    }
}

// ---------------------------------------------------------------------------

extern "C" void kernel_launch(void* const* d_in, const int* in_sizes, int n_in,
                              void* d_out, int out_size)
{
    const float* x      = (const float*)d_in[0];
    const float* W_attn = (const float*)d_in[1];
    const float* W_proj = (const float*)d_in[2];
    const float* b_proj = (const float*)d_in[3];
    float* out = (float*)d_out;

    __nv_bfloat16 *xh, *xl, *wah, *wal, *wph, *wpl, *qkvh, *qkvl, *atth, *attl;
    cudaGetSymbolAddress((void**)&xh,   g_xh);
    cudaGetSymbolAddress((void**)&xl,   g_xl);
    cudaGetSymbolAddress((void**)&wah,  g_wah);
    cudaGetSymbolAddress((void**)&wal,  g_wal);
    cudaGetSymbolAddress((void**)&wph,  g_wph);
    cudaGetSymbolAddress((void**)&wpl,  g_wpl);
    cudaGetSymbolAddress((void**)&qkvh, g_qkvh);
    cudaGetSymbolAddress((void**)&qkvl, g_qkvl);
    cudaGetSymbolAddress((void**)&atth, g_atth);
    cudaGetSymbolAddress((void**)&attl, g_attl);

    constexpr int SM192 = 2*(2*GABUF + 2*192*GROW);   // 184320
    constexpr int SM256 = 2*(2*GABUF + 2*256*GROW);   // 221184

    cudaFuncSetAttribute(gemm_mma_kernel<192>,
                         cudaFuncAttributeMaxDynamicSharedMemorySize, SM192);
    cudaFuncSetAttribute(gemm_mma_kernel<256>,
                         cudaFuncAttributeMaxDynamicSharedMemorySize, SM256);
    cudaFuncSetAttribute(attn_fa2_kernel,
                         cudaFuncAttributeMaxDynamicSharedMemorySize, ATT_SMEM);

    split_all_kernel<<<(N4_X + N4_WA + N4_WP + 255) / 256, 256>>>(
        (const float4*)x, xh, xl,
        (const float4*)W_attn, wah, wal,
        (const float4*)W_proj, wph, wpl);

    gemm_mma_kernel<192><<<dim3(16, 64), 256, SM192>>>(
        xh, xl, wah, wal, qkvh, qkvl, nullptr, nullptr, 3072, 0);

    attn_fa2_kernel<<<dim3(16, 64), 256, ATT_SMEM>>>(qkvh, qkvl, atth, attl);

    gemm_mma_kernel<256><<<dim3(4, 64), 256, SM256>>>(
        atth, attl, wph, wpl, nullptr, nullptr, out, b_proj, 1024, 1);
}

// round 16
// speedup vs baseline: 1.0708x; 1.0018x over previous
#include <cuda_runtime.h>
#include <cuda_bf16.h>
#include <math.h>
#include <cstdint>

#define NB 4
#define NT 2048
#define NC 1024
#define NH 16
#define HD 64
#define MM (NB*NT)          // 8192

// ---------------- global scratch (device globals; no runtime alloc) --------
__device__ __nv_bfloat16 g_xh[(size_t)MM*NC],    g_xl[(size_t)MM*NC];
__device__ __nv_bfloat16 g_wah[(size_t)3*NC*NC], g_wal[(size_t)3*NC*NC];
__device__ __nv_bfloat16 g_wph[(size_t)NC*NC],   g_wpl[(size_t)NC*NC];
__device__ __nv_bfloat16 g_qkvh[(size_t)MM*3*NC],g_qkvl[(size_t)MM*3*NC];
__device__ __nv_bfloat16 g_atth[(size_t)MM*NC],  g_attl[(size_t)MM*NC];

// ---------------- helpers --------------------------------------------------
__device__ __forceinline__ uint32_t s2u(const void* p) {
    return (uint32_t)__cvta_generic_to_shared(p);
}
__device__ __forceinline__ void cp16(uint32_t dst, const void* src) {
    asm volatile("cp.async.cg.shared.global [%0], [%1], 16;" :: "r"(dst), "l"(src));
}
__device__ __forceinline__ void cp_commit() {
    asm volatile("cp.async.commit_group;" ::: "memory");
}
__device__ __forceinline__ void cp_wait1() {
    asm volatile("cp.async.wait_group 1;" ::: "memory");
}
__device__ __forceinline__ void cp_wait0() {
    asm volatile("cp.async.wait_group 0;" ::: "memory");
}
__device__ __forceinline__ void ldm4(uint32_t& r0, uint32_t& r1, uint32_t& r2,
                                     uint32_t& r3, uint32_t a) {
    asm volatile("ldmatrix.sync.aligned.m8n8.x4.shared.b16 {%0,%1,%2,%3}, [%4];"
                 : "=r"(r0), "=r"(r1), "=r"(r2), "=r"(r3) : "r"(a));
}
__device__ __forceinline__ void ldm4t(uint32_t& r0, uint32_t& r1, uint32_t& r2,
                                      uint32_t& r3, uint32_t a) {
    asm volatile("ldmatrix.sync.aligned.m8n8.x4.trans.shared.b16 {%0,%1,%2,%3}, [%4];"
                 : "=r"(r0), "=r"(r1), "=r"(r2), "=r"(r3) : "r"(a));
}
__device__ __forceinline__ void mma_bf16(float* c, uint32_t a0, uint32_t a1,
                                         uint32_t a2, uint32_t a3,
                                         uint32_t b0, uint32_t b1) {
    asm volatile("mma.sync.aligned.m16n8k16.row.col.f32.bf16.bf16.f32 "
                 "{%0,%1,%2,%3}, {%4,%5,%6,%7}, {%8,%9}, {%0,%1,%2,%3};"
                 : "+f"(c[0]), "+f"(c[1]), "+f"(c[2]), "+f"(c[3])
                 : "r"(a0), "r"(a1), "r"(a2), "r"(a3), "r"(b0), "r"(b1));
}

// Fast split: one cvt.rn.bf16x2 per pair; residual via integer shifts.
__device__ __forceinline__ void pack_hilo(float x, float y, uint32_t& h, uint32_t& l)
{
    asm("cvt.rn.bf16x2.f32 %0, %1, %2;" : "=r"(h) : "f"(y), "f"(x));
    float hx = __uint_as_float(h << 16);
    float hy = __uint_as_float(h & 0xFFFF0000u);
    float rx = x - hx;
    float ry = y - hy;
    asm("cvt.rn.bf16x2.f32 %0, %1, %2;" : "=r"(l) : "f"(ry), "f"(rx));
}
__device__ __forceinline__ void split_store2(float x, float y,
                                             __nv_bfloat16* hp, __nv_bfloat16* lp)
{
    uint32_t h, l;
    pack_hilo(x, y, h, l);
    *(uint32_t*)hp = h;
    *(uint32_t*)lp = l;
}

// f32x2 packed multiply: (a,b) *= k
__device__ __forceinline__ void mul2pair(float& a, float& b, uint64_t kk)
{
    uint64_t v, r;
    asm("mov.b64 %0, {%1, %2};" : "=l"(v) : "f"(a), "f"(b));
    asm("mul.rn.f32x2 %0, %1, %2;" : "=l"(r) : "l"(v), "l"(kk));
    asm("mov.b64 {%0, %1}, %2;" : "=f"(a), "=f"(b) : "l"(r));
}
__device__ __forceinline__ uint64_t bcast2(float k)
{
    uint64_t r;
    asm("mov.b64 %0, {%1, %1};" : "=l"(r) : "f"(k));
    return r;
}

// ---------------- fused split kernel (x, W_attn, W_proj in one launch) -----
#define N4_X  2097152
#define N4_WA 786432
#define N4_WP 262144

__global__ __launch_bounds__(256) void split_all_kernel(
    const float4* __restrict__ x,  __nv_bfloat16* __restrict__ xh,  __nv_bfloat16* __restrict__ xl,
    const float4* __restrict__ wa, __nv_bfloat16* __restrict__ wah, __nv_bfloat16* __restrict__ wal,
    const float4* __restrict__ wp, __nv_bfloat16* __restrict__ wph, __nv_bfloat16* __restrict__ wpl)
{
    int i = blockIdx.x * 256 + threadIdx.x;
    const float4* src; __nv_bfloat16 *dh, *dl; int j;
    if (i < N4_X)                 { src = x;  dh = xh;  dl = xl;  j = i; }
    else if (i < N4_X + N4_WA)    { src = wa; dh = wah; dl = wal; j = i - N4_X; }
    else if (i < N4_X + N4_WA + N4_WP) { src = wp; dh = wph; dl = wpl; j = i - N4_X - N4_WA; }
    else return;
    float4 v = src[j];
    split_store2(v.x, v.y, dh + (size_t)j*4,     dl + (size_t)j*4);
    split_store2(v.z, v.w, dh + (size_t)j*4 + 2, dl + (size_t)j*4 + 2);
}

// ---------------------------------------------------------------------------
// mma.sync GEMM on pre-split bf16 (frozen R12 winner): C = A * B^T, K=1024.
// ---------------------------------------------------------------------------
#define GROW 144
#define GABUF (128*GROW)            // 18432

template<int BN>
__device__ __forceinline__ void g_load_A(
    uint32_t sbase, int st, int kt, int m0, int tid,
    const __nv_bfloat16* __restrict__ Ah, const __nv_bfloat16* __restrict__ Al)
{
    constexpr int GSTG = 2*GABUF + 2*BN*GROW;
    const int koff = kt * 64;
    const uint32_t dbase = sbase + st * GSTG;
#pragma unroll
    for (int i = 0; i < 4; i++) {
        int gidx = i * 256 + tid;
        int row = gidx >> 3, c = gidx & 7;
        uint32_t doff = row * GROW + c * 16;
        size_t soff = (size_t)(m0 + row) * 1024 + koff + c * 8;
        cp16(dbase + doff,         Ah + soff);
        cp16(dbase + GABUF + doff, Al + soff);
    }
}
template<int BN>
__device__ __forceinline__ void g_load_B(
    uint32_t sbase, int st, int kt, int n0, int tid,
    const __nv_bfloat16* __restrict__ Bh, const __nv_bfloat16* __restrict__ Bl)
{
    constexpr int GSTG = 2*GABUF + 2*BN*GROW;
    constexpr int GBBUF = BN*GROW;
    const int koff = kt * 64;
    const uint32_t dbase = sbase + st * GSTG + 2*GABUF;
#pragma unroll
    for (int i = 0; i < BN/32; i++) {
        int gidx = i * 256 + tid;
        int row = gidx >> 3, c = gidx & 7;
        uint32_t doff = row * GROW + c * 16;
        size_t soff = (size_t)(n0 + row) * 1024 + koff + c * 8;
        cp16(dbase + doff,         Bh + soff);
        cp16(dbase + GBBUF + doff, Bl + soff);
    }
}

template<int BN>
__global__ __launch_bounds__(256, 1) void gemm_mma_kernel(
    const __nv_bfloat16* __restrict__ Ah, const __nv_bfloat16* __restrict__ Al,
    const __nv_bfloat16* __restrict__ Bh, const __nv_bfloat16* __restrict__ Bl,
    __nv_bfloat16* __restrict__ outH, __nv_bfloat16* __restrict__ outL,
    float* __restrict__ outF, const float* __restrict__ bias,
    int ldc, int mode)
{
    constexpr int GBBUF = BN*GROW;
    constexpr int GSTG  = 2*GABUF + 2*GBBUF;
    constexpr int WN    = BN/4;
    constexpr int NCN   = WN/16;
    constexpr int ELD   = BN + 4;

    extern __shared__ char sm[];
    const uint32_t sbase = s2u(sm);
    const int tid  = threadIdx.x;
    const int warp = tid >> 5;
    const int lid  = tid & 31;
    const int g    = lid >> 2;
    const int qr   = lid & 3;
    const int grp  = lid >> 3;
    const int rr   = lid & 7;

    const int m0 = blockIdx.y << 7;
    const int n0 = blockIdx.x * BN;
    const int mw = (warp >> 2) * 64;
    const int nw = (warp & 3) * WN;

    const uint32_t a_rowsel = ((grp & 1) ? 8 : 0) + rr;
    const uint32_t a_colsel = (grp >= 2) ? 16 : 0;
    const uint32_t b_rowsel = ((grp >= 2) ? 8 : 0) + rr;
    const uint32_t b_colsel = (grp & 1) ? 16 : 0;

    float acc[4][2*NCN][4];
#pragma unroll
    for (int mt = 0; mt < 4; mt++)
#pragma unroll
        for (int nt = 0; nt < 2*NCN; nt++) {
            acc[mt][nt][0] = 0.f; acc[mt][nt][1] = 0.f;
            acc[mt][nt][2] = 0.f; acc[mt][nt][3] = 0.f;
        }

    g_load_A<BN>(sbase, 0, 0, m0, tid, Ah, Al);
    g_load_B<BN>(sbase, 0, 0, n0, tid, Bh, Bl);
    cp_commit();

    int stidx = 0;
    for (int kt = 0; kt < 16; kt++) {
        cp_wait0();
        __syncthreads();

        const uint32_t sb  = sbase + stidx * GSTG;
        const uint32_t sAh = sb;
        const uint32_t sAl = sb + GABUF;
        const uint32_t sBh = sb + 2*GABUF;
        const uint32_t sBl = sb + 2*GABUF + GBBUF;

        if (kt + 1 < 16)
            g_load_A<BN>(sbase, stidx ^ 1, kt + 1, m0, tid, Ah, Al);

#pragma unroll
        for (int half = 0; half < 2; half++) {
#pragma unroll
            for (int kq = 0; kq < 2; kq++) {
                const int kk = half*2 + kq;
                uint32_t ah[4][4], al[4][4];
#pragma unroll
                for (int mt = 0; mt < 4; mt++) {
                    uint32_t ra = (mw + mt*16 + a_rowsel) * GROW + kk*32 + a_colsel;
                    ldm4(ah[mt][0], ah[mt][1], ah[mt][2], ah[mt][3], sAh + ra);
                    ldm4(al[mt][0], al[mt][1], al[mt][2], al[mt][3], sAl + ra);
                }
#pragma unroll
                for (int nc = 0; nc < NCN; nc++) {
                    uint32_t rb = (nw + nc*16 + b_rowsel) * GROW + kk*32 + b_colsel;
                    uint32_t bh0, bh1, bh2, bh3, bl0, bl1, bl2, bl3;
                    ldm4(bh0, bh1, bh2, bh3, sBh + rb);
                    ldm4(bl0, bl1, bl2, bl3, sBl + rb);
#pragma unroll
                    for (int mt = 0; mt < 4; mt++) {
                        mma_bf16(acc[mt][2*nc],   ah[mt][0], ah[mt][1], ah[mt][2], ah[mt][3], bh0, bh1);
                        mma_bf16(acc[mt][2*nc+1], ah[mt][0], ah[mt][1], ah[mt][2], ah[mt][3], bh2, bh3);
                    }
#pragma unroll
                    for (int mt = 0; mt < 4; mt++) {
                        mma_bf16(acc[mt][2*nc],   ah[mt][0], ah[mt][1], ah[mt][2], ah[mt][3], bl0, bl1);
                        mma_bf16(acc[mt][2*nc+1], ah[mt][0], ah[mt][1], ah[mt][2], ah[mt][3], bl2, bl3);
                    }
#pragma unroll
                    for (int mt = 0; mt < 4; mt++) {
                        mma_bf16(acc[mt][2*nc],   al[mt][0], al[mt][1], al[mt][2], al[mt][3], bh0, bh1);
                        mma_bf16(acc[mt][2*nc+1], al[mt][0], al[mt][1], al[mt][2], al[mt][3], bh2, bh3);
                    }
                }
            }
            if (half == 0) {
                if (kt + 1 < 16)
                    g_load_B<BN>(sbase, stidx ^ 1, kt + 1, n0, tid, Bh, Bl);
                cp_commit();
            }
        }
        stidx ^= 1;
    }

    __syncthreads();
    float* Sst = (float*)sm;
#pragma unroll
    for (int mt = 0; mt < 4; mt++) {
        int row = mw + mt*16 + g;
#pragma unroll
        for (int nt = 0; nt < 2*NCN; nt++) {
            int col = nw + nt*8 + qr*2;
            *(float2*)&Sst[row*ELD + col]       = make_float2(acc[mt][nt][0], acc[mt][nt][1]);
            *(float2*)&Sst[(row+8)*ELD + col]   = make_float2(acc[mt][nt][2], acc[mt][nt][3]);
        }
    }
    __syncthreads();

    if (mode == 0) {
#pragma unroll 1
        for (int r = 0; r < 16; r++) {
            int row = warp*16 + r;
            size_t ob = (size_t)(m0 + row) * ldc + n0;
#pragma unroll
            for (int blk = 0; blk < BN/64; blk++) {
                int c = blk*64 + lid*2;
                float2 v = *(float2*)&Sst[row*ELD + c];
                split_store2(v.x, v.y, outH + ob + c, outL + ob + c);
            }
        }
    } else {
#pragma unroll 1
        for (int r = 0; r < 16; r++) {
            int row = warp*16 + r;
            size_t ob = (size_t)(m0 + row) * ldc + n0;
#pragma unroll
            for (int blk = 0; blk < BN/128; blk++) {
                int c = blk*128 + lid*4;
                float4 v = *(float4*)&Sst[row*ELD + c];
                v.x += bias[n0 + c];     v.y += bias[n0 + c + 1];
                v.z += bias[n0 + c + 2]; v.w += bias[n0 + c + 3];
                *(float4*)(outF + ob + c) = v;
            }
        }
    }
}

// ---------------------------------------------------------------------------
// Register-resident flash attention. 128 q rows, 8 warps, kv macro-tile 128.
// MMA ordering interleaves 4 accumulators per split-pass (dependency
// distance 1 -> 4) in both QK and PV. Macro-tile-shared softmax stats,
// exp2-folded softmax, deferred l-reduction, f32x2 rescale, fast packing.
// ---------------------------------------------------------------------------
#define AROW 144
#define AQ_BYTES   (128*AROW)          // 18432
#define AKV_BUF    (128*AROW)          // 18432 per tensor buffer
#define AKV_STAGE  (4*AKV_BUF)         // 73728
#define AKV_OFF    (2*AQ_BYTES)        // 36864
#define ATT_SMEM   (AKV_OFF + 2*AKV_STAGE)   // 184320
#define L2E8 11.541560327111707f       // 8 * log2(e)

__device__ __forceinline__ void attn_cp_kv(
    uint32_t sbase, int st, const __nv_bfloat16* qkvh, const __nv_bfloat16* qkvl,
    size_t rowbase, int tid)
{
    int b = tid >> 6;           // 0:Kh 1:Kl 2:Vh 3:Vl
    int r0 = tid & 63;
    const __nv_bfloat16* base = ((b & 1) ? qkvl : qkvh)
        + rowbase + ((b >> 1) ? 2048 : 1024);
    uint32_t dbuf = sbase + AKV_OFF + st*AKV_STAGE + b*AKV_BUF;
#pragma unroll
    for (int half = 0; half < 2; half++) {
        int row = r0 + half*64;
        const __nv_bfloat16* src = base + (size_t)row * 3072;
        uint32_t dst = dbuf + row*AROW;
#pragma unroll
        for (int c = 0; c < 8; c++) cp16(dst + c*16, src + c*8);
    }
    cp_commit();
}

__global__ __launch_bounds__(256) void attn_fa2_kernel(
    const __nv_bfloat16* __restrict__ qkvh, const __nv_bfloat16* __restrict__ qkvl,
    __nv_bfloat16* __restrict__ atth, __nv_bfloat16* __restrict__ attl)
{
    extern __shared__ char smraw[];
    const uint32_t sbase = s2u(smraw);

    const int tid  = threadIdx.x;
    const int warp = tid >> 5;
    const int lid  = tid & 31;
    const int g    = lid >> 2;
    const int qr   = lid & 3;
    const int grp  = lid >> 3;
    const int rr   = lid & 7;

    const int qt = (gridDim.x - 1) - blockIdx.x;   // longest tiles first
    const int bh = blockIdx.y;
    const int b_ = bh >> 4;
    const int h  = bh & 15;
    const int t0 = qt * 128;

    {
        int qb  = tid >> 7;
        int row = tid & 127;
        const __nv_bfloat16* src = (qb ? qkvl : qkvh)
            + (size_t)(b_*NT + t0 + row) * 3072 + h*HD;
        uint32_t dst = sbase + qb*AQ_BYTES + row*AROW;
#pragma unroll
        for (int c = 0; c < 8; c++) cp16(dst + c*16, src + c*8);
    }
    cp_commit();

    attn_cp_kv(sbase, 0, qkvh, qkvl, (size_t)(b_*NT) * 3072 + h*HD, tid);

    cp_wait1();
    __syncthreads();

    uint32_t aqh[4][4], aql[4][4];
    {
        uint32_t rowoff = (16*warp + ((grp & 1) ? 8 : 0) + rr) * AROW
                        + ((grp >= 2) ? 16 : 0);
#pragma unroll
        for (int kk = 0; kk < 4; kk++) {
            ldm4(aqh[kk][0], aqh[kk][1], aqh[kk][2], aqh[kk][3],
                 sbase + rowoff + kk*32);
            ldm4(aql[kk][0], aql[kk][1], aql[kk][2], aql[kk][3],
                 sbase + AQ_BYTES + rowoff + kk*32);
        }
    }

    float O[8][4];
#pragma unroll
    for (int nt = 0; nt < 8; nt++) {
        O[nt][0] = 0.f; O[nt][1] = 0.f; O[nt][2] = 0.f; O[nt][3] = 0.f;
    }
    float m0 = -1e30f, m1 = -1e30f, l0 = 0.f, l1 = 0.f;

    const int i0 = t0 + 16*warp + g;
    const int i1 = i0 + 8;
    const int njt = qt + 1;               // 128-row macro tiles

    const uint32_t k_rowsel = ((grp >= 2) ? 8 : 0) + rr;
    const uint32_t k_colsel = ((grp & 1) ? 16 : 0);
    const uint32_t v_rowsel = ((grp & 1) ? 8 : 0) + rr;
    const uint32_t v_colsel = ((grp >= 2) ? 16 : 0);

    for (int jt = 0; jt < njt; jt++) {
        const int st = jt & 1;
        if (jt + 1 < njt)
            attn_cp_kv(sbase, st ^ 1, qkvh, qkvl,
                       (size_t)(b_*NT + (jt+1)*128) * 3072 + h*HD, tid);
        if (jt + 1 < njt) cp_wait1(); else cp_wait0();
        __syncthreads();

        const uint32_t sStage = sbase + AKV_OFF + st*AKV_STAGE;
        const bool need_mask = (jt == qt);

        // ---- Phase 1: QK for BOTH subtiles; 4-way accumulator interleave --
        float Sall[2][8][4];
#pragma unroll
        for (int sub = 0; sub < 2; sub++) {
            const uint32_t soff = sub * 64 * AROW;
            const uint32_t sKh = sStage + soff;
            const uint32_t sKl = sStage + AKV_BUF + soff;
            float (*S)[4] = Sall[sub];
#pragma unroll
            for (int nt = 0; nt < 8; nt++) {
                S[nt][0] = 0.f; S[nt][1] = 0.f; S[nt][2] = 0.f; S[nt][3] = 0.f;
            }
#pragma unroll
            for (int kk = 0; kk < 4; kk++) {
#pragma unroll
                for (int npp = 0; npp < 2; npp++) {
                    uint32_t kbh[2][4], kbl[2][4];
#pragma unroll
                    for (int q = 0; q < 2; q++) {
                        uint32_t addr = ((npp*2 + q)*16 + k_rowsel)*AROW + kk*32 + k_colsel;
                        ldm4(kbh[q][0], kbh[q][1], kbh[q][2], kbh[q][3], sKh + addr);
                        ldm4(kbl[q][0], kbl[q][1], kbl[q][2], kbl[q][3], sKl + addr);
                    }
                    float (*S4)[4] = &S[npp*4];
                    // pass hh (distance-4 over S4[0..3])
                    mma_bf16(S4[0], aqh[kk][0], aqh[kk][1], aqh[kk][2], aqh[kk][3], kbh[0][0], kbh[0][1]);
                    mma_bf16(S4[1], aqh[kk][0], aqh[kk][1], aqh[kk][2], aqh[kk][3], kbh[0][2], kbh[0][3]);
                    mma_bf16(S4[2], aqh[kk][0], aqh[kk][1], aqh[kk][2], aqh[kk][3], kbh[1][0], kbh[1][1]);
                    mma_bf16(S4[3], aqh[kk][0], aqh[kk][1], aqh[kk][2], aqh[kk][3], kbh[1][2], kbh[1][3]);
                    // pass hl
                    mma_bf16(S4[0], aqh[kk][0], aqh[kk][1], aqh[kk][2], aqh[kk][3], kbl[0][0], kbl[0][1]);
                    mma_bf16(S4[1], aqh[kk][0], aqh[kk][1], aqh[kk][2], aqh[kk][3], kbl[0][2], kbl[0][3]);
                    mma_bf16(S4[2], aqh[kk][0], aqh[kk][1], aqh[kk][2], aqh[kk][3], kbl[1][0], kbl[1][1]);
                    mma_bf16(S4[3], aqh[kk][0], aqh[kk][1], aqh[kk][2], aqh[kk][3], kbl[1][2], kbl[1][3]);
                    // pass lh
                    mma_bf16(S4[0], aql[kk][0], aql[kk][1], aql[kk][2], aql[kk][3], kbh[0][0], kbh[0][1]);
                    mma_bf16(S4[1], aql[kk][0], aql[kk][1], aql[kk][2], aql[kk][3], kbh[0][2], kbh[0][3]);
                    mma_bf16(S4[2], aql[kk][0], aql[kk][1], aql[kk][2], aql[kk][3], kbh[1][0], kbh[1][1]);
                    mma_bf16(S4[3], aql[kk][0], aql[kk][1], aql[kk][2], aql[kk][3], kbh[1][2], kbh[1][3]);
                }
            }
        }

        // ---- Phase 2a: mask (raw logit domain) ----
        if (need_mask) {
#pragma unroll
            for (int sub = 0; sub < 2; sub++) {
                float (*S)[4] = Sall[sub];
                const int jbase = jt*128 + sub*64;
#pragma unroll
                for (int nt = 0; nt < 8; nt++) {
                    int jb = jbase + nt*8 + qr*2;
                    if (jb     > i0) S[nt][0] = -1e30f;
                    if (jb + 1 > i0) S[nt][1] = -1e30f;
                    if (jb     > i1) S[nt][2] = -1e30f;
                    if (jb + 1 > i1) S[nt][3] = -1e30f;
                }
            }
        }

        // ---- Phase 2b: single max / corr / O-rescale over the macro tile --
        float mx0 = -1e30f, mx1 = -1e30f;
#pragma unroll
        for (int sub = 0; sub < 2; sub++) {
            float (*S)[4] = Sall[sub];
#pragma unroll
            for (int nt = 0; nt < 8; nt++) {
                mx0 = fmaxf(mx0, fmaxf(S[nt][0], S[nt][1]));
                mx1 = fmaxf(mx1, fmaxf(S[nt][2], S[nt][3]));
            }
        }
        mx0 = fmaxf(mx0, __shfl_xor_sync(0xffffffffu, mx0, 1));
        mx0 = fmaxf(mx0, __shfl_xor_sync(0xffffffffu, mx0, 2));
        mx1 = fmaxf(mx1, __shfl_xor_sync(0xffffffffu, mx1, 1));
        mx1 = fmaxf(mx1, __shfl_xor_sync(0xffffffffu, mx1, 2));

        float mn0 = fmaxf(m0, mx0), mn1 = fmaxf(m1, mx1);
        float corr0 = exp2f((m0 - mn0) * L2E8);
        float corr1 = exp2f((m1 - mn1) * L2E8);
        m0 = mn0; m1 = mn1;
        const float c0 = mn0 * L2E8;
        const float c1 = mn1 * L2E8;

        {
            uint64_t cc0 = bcast2(corr0), cc1 = bcast2(corr1);
#pragma unroll
            for (int nt = 0; nt < 8; nt++) {
                mul2pair(O[nt][0], O[nt][1], cc0);
                mul2pair(O[nt][2], O[nt][3], cc1);
            }
        }
        l0 *= corr0;
        l1 *= corr1;

        // ---- Phase 2c+d: per-sub exp + pack + PV (4-way acc interleave) ---
#pragma unroll
        for (int sub = 0; sub < 2; sub++) {
            const uint32_t soff = sub * 64 * AROW;
            const uint32_t sVh = sStage + 2*AKV_BUF + soff;
            const uint32_t sVl = sStage + 3*AKV_BUF + soff;
            float (*S)[4] = Sall[sub];

            float sum0 = 0.f, sum1 = 0.f;
#pragma unroll
            for (int nt = 0; nt < 8; nt++) {
                float p0 = exp2f(fmaf(S[nt][0], L2E8, -c0));
                float p1 = exp2f(fmaf(S[nt][1], L2E8, -c0));
                float p2 = exp2f(fmaf(S[nt][2], L2E8, -c1));
                float p3 = exp2f(fmaf(S[nt][3], L2E8, -c1));
                sum0 += p0 + p1; sum1 += p2 + p3;
                S[nt][0] = p0; S[nt][1] = p1; S[nt][2] = p2; S[nt][3] = p3;
            }
            l0 += sum0;
            l1 += sum1;

#pragma unroll
            for (int kk = 0; kk < 4; kk++) {
                uint32_t ah0, ah1, ah2, ah3, al0, al1, al2, al3;
                pack_hilo(S[2*kk][0],   S[2*kk][1],   ah0, al0);
                pack_hilo(S[2*kk][2],   S[2*kk][3],   ah1, al1);
                pack_hilo(S[2*kk+1][0], S[2*kk+1][1], ah2, al2);
                pack_hilo(S[2*kk+1][2], S[2*kk+1][3], ah3, al3);
#pragma unroll
                for (int npp = 0; npp < 2; npp++) {
                    uint32_t vbh[2][4], vbl[2][4];
#pragma unroll
                    for (int q = 0; q < 2; q++) {
                        uint32_t addr = (kk*16 + v_rowsel)*AROW + (npp*2 + q)*32 + v_colsel;
                        ldm4t(vbh[q][0], vbh[q][1], vbh[q][2], vbh[q][3], sVh + addr);
                        ldm4t(vbl[q][0], vbl[q][1], vbl[q][2], vbl[q][3], sVl + addr);
                    }
                    float (*O4)[4] = &O[npp*4];
                    // pass hh (distance-4 over O4[0..3])
                    mma_bf16(O4[0], ah0, ah1, ah2, ah3, vbh[0][0], vbh[0][1]);
                    mma_bf16(O4[1], ah0, ah1, ah2, ah3, vbh[0][2], vbh[0][3]);
                    mma_bf16(O4[2], ah0, ah1, ah2, ah3, vbh[1][0], vbh[1][1]);
                    mma_bf16(O4[3], ah0, ah1, ah2, ah3, vbh[1][2], vbh[1][3]);
                    // pass hl
                    mma_bf16(O4[0], ah0, ah1, ah2, ah3, vbl[0][0], vbl[0][1]);
                    mma_bf16(O4[1], ah0, ah1, ah2, ah3, vbl[0][2], vbl[0][3]);
                    mma_bf16(O4[2], ah0, ah1, ah2, ah3, vbl[1][0], vbl[1][1]);
                    mma_bf16(O4[3], ah0, ah1, ah2, ah3, vbl[1][2], vbl[1][3]);
                    // pass lh
                    mma_bf16(O4[0], al0, al1, al2, al3, vbh[0][0], vbh[0][1]);
                    mma_bf16(O4[1], al0, al1, al2, al3, vbh[0][2], vbh[0][3]);
                    mma_bf16(O4[2], al0, al1, al2, al3, vbh[1][0], vbh[1][1]);
                    mma_bf16(O4[3], al0, al1, al2, al3, vbh[1][2], vbh[1][3]);
                }
            }
        }
        __syncthreads();
    }

    // final quad reduction of partial l, then normalize + store
    l0 += __shfl_xor_sync(0xffffffffu, l0, 1);
    l0 += __shfl_xor_sync(0xffffffffu, l0, 2);
    l1 += __shfl_xor_sync(0xffffffffu, l1, 1);
    l1 += __shfl_xor_sync(0xffffffffu, l1, 2);

    float inv0 = 1.f / l0, inv1 = 1.f / l1;
    size_t r0 = (size_t)(b_*NT + i0) * NC + h*HD + qr*2;
    size_t r1 = (size_t)(b_*NT + i1) * NC + h*HD + qr*2;
#pragma unroll
    for (int nt = 0; nt < 8; nt++) {
        split_store2(O[nt][0]*inv0, O[nt][1]*inv0, atth + r0 + nt*8, attl + r0 + nt*8);
        split_store2(O[nt][2]*inv1, O[nt][3]*inv1, atth + r1 + nt*8, attl + r1 + nt*8);
    }
}

// ---------------------------------------------------------------------------

extern "C" void kernel_launch(void* const* d_in, const int* in_sizes, int n_in,
                              void* d_out, int out_size)
{
    const float* x      = (const float*)d_in[0];
    const float* W_attn = (const float*)d_in[1];
    const float* W_proj = (const float*)d_in[2];
    const float* b_proj = (const float*)d_in[3];
    float* out = (float*)d_out;

    __nv_bfloat16 *xh, *xl, *wah, *wal, *wph, *wpl, *qkvh, *qkvl, *atth, *attl;
    cudaGetSymbolAddress((void**)&xh,   g_xh);
    cudaGetSymbolAddress((void**)&xl,   g_xl);
    cudaGetSymbolAddress((void**)&wah,  g_wah);
    cudaGetSymbolAddress((void**)&wal,  g_wal);
    cudaGetSymbolAddress((void**)&wph,  g_wph);
    cudaGetSymbolAddress((void**)&wpl,  g_wpl);
    cudaGetSymbolAddress((void**)&qkvh, g_qkvh);
    cudaGetSymbolAddress((void**)&qkvl, g_qkvl);
    cudaGetSymbolAddress((void**)&atth, g_atth);
    cudaGetSymbolAddress((void**)&attl, g_attl);

    constexpr int SM192 = 2*(2*GABUF + 2*192*GROW);   // 184320
    constexpr int SM256 = 2*(2*GABUF + 2*256*GROW);   // 221184

    cudaFuncSetAttribute(gemm_mma_kernel<192>,
                         cudaFuncAttributeMaxDynamicSharedMemorySize, SM192);
    cudaFuncSetAttribute(gemm_mma_kernel<256>,
                         cudaFuncAttributeMaxDynamicSharedMemorySize, SM256);
    cudaFuncSetAttribute(attn_fa2_kernel,
                         cudaFuncAttributeMaxDynamicSharedMemorySize, ATT_SMEM);

    split_all_kernel<<<(N4_X + N4_WA + N4_WP + 255) / 256, 256>>>(
        (const float4*)x, xh, xl,
        (const float4*)W_attn, wah, wal,
        (const float4*)W_proj, wph, wpl);

    gemm_mma_kernel<192><<<dim3(16, 64), 256, SM192>>>(
        xh, xl, wah, wal, qkvh, qkvl, nullptr, nullptr, 3072, 0);

    attn_fa2_kernel<<<dim3(16, 64), 256, ATT_SMEM>>>(qkvh, qkvl, atth, attl);

    gemm_mma_kernel<256><<<dim3(4, 64), 256, SM256>>>(
        atth, attl, wph, wpl, nullptr, nullptr, out, b_proj, 1024, 1);
}

// round 17
// speedup vs baseline: 1.1515x; 1.0754x over previous
#include <cuda_runtime.h>
#include <cuda_bf16.h>
#include <cuda_fp16.h>
#include <math.h>
#include <cstdint>

#define NB 4
#define NT 2048
#define NC 1024
#define NH 16
#define HD 64
#define MM (NB*NT)          // 8192

// ---------------- global scratch (device globals; no runtime alloc) --------
__device__ __nv_bfloat16 g_xh[(size_t)MM*NC],    g_xl[(size_t)MM*NC];
__device__ __nv_bfloat16 g_wah[(size_t)3*NC*NC], g_wal[(size_t)3*NC*NC];
__device__ __nv_bfloat16 g_wph[(size_t)NC*NC],   g_wpl[(size_t)NC*NC];
__device__ __nv_bfloat16 g_qkvh[(size_t)MM*3*NC],g_qkvl[(size_t)MM*3*NC];
__device__ __half        g_v16[(size_t)MM*NC];   // V as single fp16
__device__ __nv_bfloat16 g_atth[(size_t)MM*NC],  g_attl[(size_t)MM*NC];

// ---------------- helpers --------------------------------------------------
__device__ __forceinline__ uint32_t s2u(const void* p) {
    return (uint32_t)__cvta_generic_to_shared(p);
}
__device__ __forceinline__ void cp16(uint32_t dst, const void* src) {
    asm volatile("cp.async.cg.shared.global [%0], [%1], 16;" :: "r"(dst), "l"(src));
}
__device__ __forceinline__ void cp_commit() {
    asm volatile("cp.async.commit_group;" ::: "memory");
}
__device__ __forceinline__ void cp_wait1() {
    asm volatile("cp.async.wait_group 1;" ::: "memory");
}
__device__ __forceinline__ void cp_wait0() {
    asm volatile("cp.async.wait_group 0;" ::: "memory");
}
__device__ __forceinline__ void ldm4(uint32_t& r0, uint32_t& r1, uint32_t& r2,
                                     uint32_t& r3, uint32_t a) {
    asm volatile("ldmatrix.sync.aligned.m8n8.x4.shared.b16 {%0,%1,%2,%3}, [%4];"
                 : "=r"(r0), "=r"(r1), "=r"(r2), "=r"(r3) : "r"(a));
}
__device__ __forceinline__ void ldm4t(uint32_t& r0, uint32_t& r1, uint32_t& r2,
                                      uint32_t& r3, uint32_t a) {
    asm volatile("ldmatrix.sync.aligned.m8n8.x4.trans.shared.b16 {%0,%1,%2,%3}, [%4];"
                 : "=r"(r0), "=r"(r1), "=r"(r2), "=r"(r3) : "r"(a));
}
__device__ __forceinline__ void mma_bf16(float* c, uint32_t a0, uint32_t a1,
                                         uint32_t a2, uint32_t a3,
                                         uint32_t b0, uint32_t b1) {
    asm volatile("mma.sync.aligned.m16n8k16.row.col.f32.bf16.bf16.f32 "
                 "{%0,%1,%2,%3}, {%4,%5,%6,%7}, {%8,%9}, {%0,%1,%2,%3};"
                 : "+f"(c[0]), "+f"(c[1]), "+f"(c[2]), "+f"(c[3])
                 : "r"(a0), "r"(a1), "r"(a2), "r"(a3), "r"(b0), "r"(b1));
}
__device__ __forceinline__ void mma_f16(float* c, uint32_t a0, uint32_t a1,
                                        uint32_t a2, uint32_t a3,
                                        uint32_t b0, uint32_t b1) {
    asm volatile("mma.sync.aligned.m16n8k16.row.col.f32.f16.f16.f32 "
                 "{%0,%1,%2,%3}, {%4,%5,%6,%7}, {%8,%9}, {%0,%1,%2,%3};"
                 : "+f"(c[0]), "+f"(c[1]), "+f"(c[2]), "+f"(c[3])
                 : "r"(a0), "r"(a1), "r"(a2), "r"(a3), "r"(b0), "r"(b1));
}

// Fast split: one cvt.rn.bf16x2 per pair; residual via integer shifts.
__device__ __forceinline__ void pack_hilo(float x, float y, uint32_t& h, uint32_t& l)
{
    asm("cvt.rn.bf16x2.f32 %0, %1, %2;" : "=r"(h) : "f"(y), "f"(x));
    float hx = __uint_as_float(h << 16);
    float hy = __uint_as_float(h & 0xFFFF0000u);
    float rx = x - hx;
    float ry = y - hy;
    asm("cvt.rn.bf16x2.f32 %0, %1, %2;" : "=r"(l) : "f"(ry), "f"(rx));
}
__device__ __forceinline__ void split_store2(float x, float y,
                                             __nv_bfloat16* hp, __nv_bfloat16* lp)
{
    uint32_t h, l;
    pack_hilo(x, y, h, l);
    *(uint32_t*)hp = h;
    *(uint32_t*)lp = l;
}
// fp16 hi/lo pair pack (split residual ~2^-22: effectively exact)
__device__ __forceinline__ void pack_f16_hilo(float x, float y, uint32_t& h, uint32_t& l)
{
    asm("cvt.rn.f16x2.f32 %0, %1, %2;" : "=r"(h) : "f"(y), "f"(x));
    __half2 hv = *(__half2*)&h;
    float hx = __low2float(hv), hy = __high2float(hv);
    float rx = x - hx, ry = y - hy;
    asm("cvt.rn.f16x2.f32 %0, %1, %2;" : "=r"(l) : "f"(ry), "f"(rx));
}

// f32x2 packed multiply: (a,b) *= k
__device__ __forceinline__ void mul2pair(float& a, float& b, uint64_t kk)
{
    uint64_t v, r;
    asm("mov.b64 %0, {%1, %2};" : "=l"(v) : "f"(a), "f"(b));
    asm("mul.rn.f32x2 %0, %1, %2;" : "=l"(r) : "l"(v), "l"(kk));
    asm("mov.b64 {%0, %1}, %2;" : "=f"(a), "=f"(b) : "l"(r));
}
__device__ __forceinline__ uint64_t bcast2(float k)
{
    uint64_t r;
    asm("mov.b64 %0, {%1, %1};" : "=l"(r) : "f"(k));
    return r;
}

// ---------------- fused split kernel (x, W_attn, W_proj in one launch) -----
#define N4_X  2097152
#define N4_WA 786432
#define N4_WP 262144

__global__ __launch_bounds__(256) void split_all_kernel(
    const float4* __restrict__ x,  __nv_bfloat16* __restrict__ xh,  __nv_bfloat16* __restrict__ xl,
    const float4* __restrict__ wa, __nv_bfloat16* __restrict__ wah, __nv_bfloat16* __restrict__ wal,
    const float4* __restrict__ wp, __nv_bfloat16* __restrict__ wph, __nv_bfloat16* __restrict__ wpl)
{
    int i = blockIdx.x * 256 + threadIdx.x;
    const float4* src; __nv_bfloat16 *dh, *dl; int j;
    if (i < N4_X)                 { src = x;  dh = xh;  dl = xl;  j = i; }
    else if (i < N4_X + N4_WA)    { src = wa; dh = wah; dl = wal; j = i - N4_X; }
    else if (i < N4_X + N4_WA + N4_WP) { src = wp; dh = wph; dl = wpl; j = i - N4_X - N4_WA; }
    else return;
    float4 v = src[j];
    split_store2(v.x, v.y, dh + (size_t)j*4,     dl + (size_t)j*4);
    split_store2(v.z, v.w, dh + (size_t)j*4 + 2, dl + (size_t)j*4 + 2);
}

// ---------------------------------------------------------------------------
// mma.sync GEMM on pre-split bf16: C = A * B^T, K=1024. Templated on BN.
// mode 0: bf16 hi/lo out; columns >= 2048 (the V block of QKV) additionally
// routed to outV as single fp16.  mode 1: f32 + bias out.
// ---------------------------------------------------------------------------
#define GROW 144
#define GABUF (128*GROW)            // 18432

template<int BN>
__device__ __forceinline__ void g_load_A(
    uint32_t sbase, int st, int kt, int m0, int tid,
    const __nv_bfloat16* __restrict__ Ah, const __nv_bfloat16* __restrict__ Al)
{
    constexpr int GSTG = 2*GABUF + 2*BN*GROW;
    const int koff = kt * 64;
    const uint32_t dbase = sbase + st * GSTG;
#pragma unroll
    for (int i = 0; i < 4; i++) {
        int gidx = i * 256 + tid;
        int row = gidx >> 3, c = gidx & 7;
        uint32_t doff = row * GROW + c * 16;
        size_t soff = (size_t)(m0 + row) * 1024 + koff + c * 8;
        cp16(dbase + doff,         Ah + soff);
        cp16(dbase + GABUF + doff, Al + soff);
    }
}
template<int BN>
__device__ __forceinline__ void g_load_B(
    uint32_t sbase, int st, int kt, int n0, int tid,
    const __nv_bfloat16* __restrict__ Bh, const __nv_bfloat16* __restrict__ Bl)
{
    constexpr int GSTG = 2*GABUF + 2*BN*GROW;
    constexpr int GBBUF = BN*GROW;
    const int koff = kt * 64;
    const uint32_t dbase = sbase + st * GSTG + 2*GABUF;
#pragma unroll
    for (int i = 0; i < BN/32; i++) {
        int gidx = i * 256 + tid;
        int row = gidx >> 3, c = gidx & 7;
        uint32_t doff = row * GROW + c * 16;
        size_t soff = (size_t)(n0 + row) * 1024 + koff + c * 8;
        cp16(dbase + doff,         Bh + soff);
        cp16(dbase + GBBUF + doff, Bl + soff);
    }
}

template<int BN>
__global__ __launch_bounds__(256, 1) void gemm_mma_kernel(
    const __nv_bfloat16* __restrict__ Ah, const __nv_bfloat16* __restrict__ Al,
    const __nv_bfloat16* __restrict__ Bh, const __nv_bfloat16* __restrict__ Bl,
    __nv_bfloat16* __restrict__ outH, __nv_bfloat16* __restrict__ outL,
    __half* __restrict__ outV,
    float* __restrict__ outF, const float* __restrict__ bias,
    int ldc, int mode)
{
    constexpr int GBBUF = BN*GROW;
    constexpr int GSTG  = 2*GABUF + 2*GBBUF;
    constexpr int WN    = BN/4;
    constexpr int NCN   = WN/16;
    constexpr int ELD   = BN + 4;

    extern __shared__ char sm[];
    const uint32_t sbase = s2u(sm);
    const int tid  = threadIdx.x;
    const int warp = tid >> 5;
    const int lid  = tid & 31;
    const int g    = lid >> 2;
    const int qr   = lid & 3;
    const int grp  = lid >> 3;
    const int rr   = lid & 7;

    const int m0 = blockIdx.y << 7;
    const int n0 = blockIdx.x * BN;
    const int mw = (warp >> 2) * 64;
    const int nw = (warp & 3) * WN;

    const uint32_t a_rowsel = ((grp & 1) ? 8 : 0) + rr;
    const uint32_t a_colsel = (grp >= 2) ? 16 : 0;
    const uint32_t b_rowsel = ((grp >= 2) ? 8 : 0) + rr;
    const uint32_t b_colsel = (grp & 1) ? 16 : 0;

    float acc[4][2*NCN][4];
#pragma unroll
    for (int mt = 0; mt < 4; mt++)
#pragma unroll
        for (int nt = 0; nt < 2*NCN; nt++) {
            acc[mt][nt][0] = 0.f; acc[mt][nt][1] = 0.f;
            acc[mt][nt][2] = 0.f; acc[mt][nt][3] = 0.f;
        }

    g_load_A<BN>(sbase, 0, 0, m0, tid, Ah, Al);
    g_load_B<BN>(sbase, 0, 0, n0, tid, Bh, Bl);
    cp_commit();

    int stidx = 0;
    for (int kt = 0; kt < 16; kt++) {
        cp_wait0();
        __syncthreads();

        const uint32_t sb  = sbase + stidx * GSTG;
        const uint32_t sAh = sb;
        const uint32_t sAl = sb + GABUF;
        const uint32_t sBh = sb + 2*GABUF;
        const uint32_t sBl = sb + 2*GABUF + GBBUF;

        if (kt + 1 < 16)
            g_load_A<BN>(sbase, stidx ^ 1, kt + 1, m0, tid, Ah, Al);

#pragma unroll
        for (int half = 0; half < 2; half++) {
#pragma unroll
            for (int kq = 0; kq < 2; kq++) {
                const int kk = half*2 + kq;
                uint32_t ah[4][4], al[4][4];
#pragma unroll
                for (int mt = 0; mt < 4; mt++) {
                    uint32_t ra = (mw + mt*16 + a_rowsel) * GROW + kk*32 + a_colsel;
                    ldm4(ah[mt][0], ah[mt][1], ah[mt][2], ah[mt][3], sAh + ra);
                    ldm4(al[mt][0], al[mt][1], al[mt][2], al[mt][3], sAl + ra);
                }
#pragma unroll
                for (int nc = 0; nc < NCN; nc++) {
                    uint32_t rb = (nw + nc*16 + b_rowsel) * GROW + kk*32 + b_colsel;
                    uint32_t bh0, bh1, bh2, bh3, bl0, bl1, bl2, bl3;
                    ldm4(bh0, bh1, bh2, bh3, sBh + rb);
                    ldm4(bl0, bl1, bl2, bl3, sBl + rb);
#pragma unroll
                    for (int mt = 0; mt < 4; mt++) {
                        mma_bf16(acc[mt][2*nc],   ah[mt][0], ah[mt][1], ah[mt][2], ah[mt][3], bh0, bh1);
                        mma_bf16(acc[mt][2*nc+1], ah[mt][0], ah[mt][1], ah[mt][2], ah[mt][3], bh2, bh3);
                    }
#pragma unroll
                    for (int mt = 0; mt < 4; mt++) {
                        mma_bf16(acc[mt][2*nc],   ah[mt][0], ah[mt][1], ah[mt][2], ah[mt][3], bl0, bl1);
                        mma_bf16(acc[mt][2*nc+1], ah[mt][0], ah[mt][1], ah[mt][2], ah[mt][3], bl2, bl3);
                    }
#pragma unroll
                    for (int mt = 0; mt < 4; mt++) {
                        mma_bf16(acc[mt][2*nc],   al[mt][0], al[mt][1], al[mt][2], al[mt][3], bh0, bh1);
                        mma_bf16(acc[mt][2*nc+1], al[mt][0], al[mt][1], al[mt][2], al[mt][3], bh2, bh3);
                    }
                }
            }
            if (half == 0) {
                if (kt + 1 < 16)
                    g_load_B<BN>(sbase, stidx ^ 1, kt + 1, n0, tid, Bh, Bl);
                cp_commit();
            }
        }
        stidx ^= 1;
    }

    __syncthreads();
    float* Sst = (float*)sm;
#pragma unroll
    for (int mt = 0; mt < 4; mt++) {
        int row = mw + mt*16 + g;
#pragma unroll
        for (int nt = 0; nt < 2*NCN; nt++) {
            int col = nw + nt*8 + qr*2;
            *(float2*)&Sst[row*ELD + col]       = make_float2(acc[mt][nt][0], acc[mt][nt][1]);
            *(float2*)&Sst[(row+8)*ELD + col]   = make_float2(acc[mt][nt][2], acc[mt][nt][3]);
        }
    }
    __syncthreads();

    if (mode == 0) {
#pragma unroll 1
        for (int r = 0; r < 16; r++) {
            int row = warp*16 + r;
#pragma unroll
            for (int blk = 0; blk < BN/64; blk++) {
                int c = blk*64 + lid*2;
                int n = n0 + c;
                float2 v = *(float2*)&Sst[row*ELD + c];
                if (outV && n >= 2048) {
                    // V block: single fp16
                    *(__half2*)(outV + (size_t)(m0 + row) * 1024 + (n - 2048)) =
                        __floats2half2_rn(v.x, v.y);
                } else {
                    size_t ob = (size_t)(m0 + row) * ldc + n;
                    split_store2(v.x, v.y, outH + ob, outL + ob);
                }
            }
        }
    } else {
#pragma unroll 1
        for (int r = 0; r < 16; r++) {
            int row = warp*16 + r;
            size_t ob = (size_t)(m0 + row) * ldc + n0;
#pragma unroll
            for (int blk = 0; blk < BN/128; blk++) {
                int c = blk*128 + lid*4;
                float4 v = *(float4*)&Sst[row*ELD + c];
                v.x += bias[n0 + c];     v.y += bias[n0 + c + 1];
                v.z += bias[n0 + c + 2]; v.w += bias[n0 + c + 3];
                *(float4*)(outF + ob + c) = v;
            }
        }
    }
}

// ---------------------------------------------------------------------------
// Register-resident flash attention. 128 q rows, 8 warps, kv macro-tile 128.
// QK: bf16 3-pass (precision-critical). PV: fp16 2-pass (P split into fp16
// hi/lo, V single fp16) -> 17% fewer HMMA, half the V ldsm, 25% less smem.
// Macro-shared softmax stats, exp2-folded, deferred l-reduction.
// ---------------------------------------------------------------------------
#define AROW 144
#define AQ_BYTES   (128*AROW)          // 18432
#define AKV_BUF    (128*AROW)          // 18432 per tensor buffer
#define AKV_STAGE  (3*AKV_BUF)         // 55296 (Kh, Kl, V16)
#define AKV_OFF    (2*AQ_BYTES)        // 36864
#define ATT_SMEM   (AKV_OFF + 2*AKV_STAGE)   // 147456
#define L2E8 11.541560327111707f       // 8 * log2(e)

__device__ __forceinline__ void attn_cp_kv(
    uint32_t sbase, int st, const __nv_bfloat16* qkvh, const __nv_bfloat16* qkvl,
    const __half* v16, size_t krowbase, size_t vrowbase, int tid)
{
    const uint32_t dstage = sbase + AKV_OFF + st*AKV_STAGE;
    if (tid < 128) {
        // K hi/lo: 64 threads each, 2 rows per thread
        int b = tid >> 6;          // 0:Kh 1:Kl
        int r0 = tid & 63;
        const __nv_bfloat16* base = (b ? qkvl : qkvh) + krowbase + 1024;
        uint32_t dbuf = dstage + b*AKV_BUF;
#pragma unroll
        for (int half = 0; half < 2; half++) {
            int row = r0 + half*64;
            const __nv_bfloat16* src = base + (size_t)row * 3072;
            uint32_t dst = dbuf + row*AROW;
#pragma unroll
            for (int c = 0; c < 8; c++) cp16(dst + c*16, src + c*8);
        }
    } else {
        // V fp16: 128 threads, 1 row (128 B) each
        int row = tid - 128;
        const __half* src = v16 + vrowbase + (size_t)row * 1024;
        uint32_t dst = dstage + 2*AKV_BUF + row*AROW;
#pragma unroll
        for (int c = 0; c < 8; c++) cp16(dst + c*16, src + c*8);
    }
    cp_commit();
}

__global__ __launch_bounds__(256) void attn_fa2_kernel(
    const __nv_bfloat16* __restrict__ qkvh, const __nv_bfloat16* __restrict__ qkvl,
    const __half* __restrict__ v16,
    __nv_bfloat16* __restrict__ atth, __nv_bfloat16* __restrict__ attl)
{
    extern __shared__ char smraw[];
    const uint32_t sbase = s2u(smraw);

    const int tid  = threadIdx.x;
    const int warp = tid >> 5;
    const int lid  = tid & 31;
    const int g    = lid >> 2;
    const int qr   = lid & 3;
    const int grp  = lid >> 3;
    const int rr   = lid & 7;

    const int qt = (gridDim.x - 1) - blockIdx.x;   // longest tiles first
    const int bh = blockIdx.y;
    const int b_ = bh >> 4;
    const int h  = bh & 15;
    const int t0 = qt * 128;

    {
        int qb  = tid >> 7;
        int row = tid & 127;
        const __nv_bfloat16* src = (qb ? qkvl : qkvh)
            + (size_t)(b_*NT + t0 + row) * 3072 + h*HD;
        uint32_t dst = sbase + qb*AQ_BYTES + row*AROW;
#pragma unroll
        for (int c = 0; c < 8; c++) cp16(dst + c*16, src + c*8);
    }
    cp_commit();

    attn_cp_kv(sbase, 0, qkvh, qkvl, v16,
               (size_t)(b_*NT) * 3072 + h*HD,
               (size_t)(b_*NT) * 1024 + h*HD, tid);

    cp_wait1();
    __syncthreads();

    uint32_t aqh[4][4], aql[4][4];
    {
        uint32_t rowoff = (16*warp + ((grp & 1) ? 8 : 0) + rr) * AROW
                        + ((grp >= 2) ? 16 : 0);
#pragma unroll
        for (int kk = 0; kk < 4; kk++) {
            ldm4(aqh[kk][0], aqh[kk][1], aqh[kk][2], aqh[kk][3],
                 sbase + rowoff + kk*32);
            ldm4(aql[kk][0], aql[kk][1], aql[kk][2], aql[kk][3],
                 sbase + AQ_BYTES + rowoff + kk*32);
        }
    }

    float O[8][4];
#pragma unroll
    for (int nt = 0; nt < 8; nt++) {
        O[nt][0] = 0.f; O[nt][1] = 0.f; O[nt][2] = 0.f; O[nt][3] = 0.f;
    }
    float m0 = -1e30f, m1 = -1e30f, l0 = 0.f, l1 = 0.f;

    const int i0 = t0 + 16*warp + g;
    const int i1 = i0 + 8;
    const int njt = qt + 1;               // 128-row macro tiles

    const uint32_t k_rowsel = ((grp >= 2) ? 8 : 0) + rr;
    const uint32_t k_colsel = ((grp & 1) ? 16 : 0);
    const uint32_t v_rowsel = ((grp & 1) ? 8 : 0) + rr;
    const uint32_t v_colsel = ((grp >= 2) ? 16 : 0);

    for (int jt = 0; jt < njt; jt++) {
        const int st = jt & 1;
        if (jt + 1 < njt)
            attn_cp_kv(sbase, st ^ 1, qkvh, qkvl, v16,
                       (size_t)(b_*NT + (jt+1)*128) * 3072 + h*HD,
                       (size_t)(b_*NT + (jt+1)*128) * 1024 + h*HD, tid);
        if (jt + 1 < njt) cp_wait1(); else cp_wait0();
        __syncthreads();

        const uint32_t sStage = sbase + AKV_OFF + st*AKV_STAGE;
        const uint32_t sV = sStage + 2*AKV_BUF;
        const bool need_mask = (jt == qt);

        // ---- Phase 1: QK (bf16 3-pass) for both subtiles ----
        float Sall[2][8][4];
#pragma unroll
        for (int sub = 0; sub < 2; sub++) {
            const uint32_t soff = sub * 64 * AROW;
            const uint32_t sKh = sStage + soff;
            const uint32_t sKl = sStage + AKV_BUF + soff;
            float (*S)[4] = Sall[sub];
#pragma unroll
            for (int nt = 0; nt < 8; nt++) {
                S[nt][0] = 0.f; S[nt][1] = 0.f; S[nt][2] = 0.f; S[nt][3] = 0.f;
            }
#pragma unroll
            for (int kk = 0; kk < 4; kk++) {
#pragma unroll
                for (int npp = 0; npp < 2; npp++) {
                    uint32_t kbh[2][4], kbl[2][4];
#pragma unroll
                    for (int q = 0; q < 2; q++) {
                        uint32_t addr = ((npp*2 + q)*16 + k_rowsel)*AROW + kk*32 + k_colsel;
                        ldm4(kbh[q][0], kbh[q][1], kbh[q][2], kbh[q][3], sKh + addr);
                        ldm4(kbl[q][0], kbl[q][1], kbl[q][2], kbl[q][3], sKl + addr);
                    }
                    float (*S4)[4] = &S[npp*4];
                    mma_bf16(S4[0], aqh[kk][0], aqh[kk][1], aqh[kk][2], aqh[kk][3], kbh[0][0], kbh[0][1]);
                    mma_bf16(S4[1], aqh[kk][0], aqh[kk][1], aqh[kk][2], aqh[kk][3], kbh[0][2], kbh[0][3]);
                    mma_bf16(S4[2], aqh[kk][0], aqh[kk][1], aqh[kk][2], aqh[kk][3], kbh[1][0], kbh[1][1]);
                    mma_bf16(S4[3], aqh[kk][0], aqh[kk][1], aqh[kk][2], aqh[kk][3], kbh[1][2], kbh[1][3]);
                    mma_bf16(S4[0], aqh[kk][0], aqh[kk][1], aqh[kk][2], aqh[kk][3], kbl[0][0], kbl[0][1]);
                    mma_bf16(S4[1], aqh[kk][0], aqh[kk][1], aqh[kk][2], aqh[kk][3], kbl[0][2], kbl[0][3]);
                    mma_bf16(S4[2], aqh[kk][0], aqh[kk][1], aqh[kk][2], aqh[kk][3], kbl[1][0], kbl[1][1]);
                    mma_bf16(S4[3], aqh[kk][0], aqh[kk][1], aqh[kk][2], aqh[kk][3], kbl[1][2], kbl[1][3]);
                    mma_bf16(S4[0], aql[kk][0], aql[kk][1], aql[kk][2], aql[kk][3], kbh[0][0], kbh[0][1]);
                    mma_bf16(S4[1], aql[kk][0], aql[kk][1], aql[kk][2], aql[kk][3], kbh[0][2], kbh[0][3]);
                    mma_bf16(S4[2], aql[kk][0], aql[kk][1], aql[kk][2], aql[kk][3], kbh[1][0], kbh[1][1]);
                    mma_bf16(S4[3], aql[kk][0], aql[kk][1], aql[kk][2], aql[kk][3], kbh[1][2], kbh[1][3]);
                }
            }
        }

        // ---- Phase 2a: mask ----
        if (need_mask) {
#pragma unroll
            for (int sub = 0; sub < 2; sub++) {
                float (*S)[4] = Sall[sub];
                const int jbase = jt*128 + sub*64;
#pragma unroll
                for (int nt = 0; nt < 8; nt++) {
                    int jb = jbase + nt*8 + qr*2;
                    if (jb     > i0) S[nt][0] = -1e30f;
                    if (jb + 1 > i0) S[nt][1] = -1e30f;
                    if (jb     > i1) S[nt][2] = -1e30f;
                    if (jb + 1 > i1) S[nt][3] = -1e30f;
                }
            }
        }

        // ---- Phase 2b: single max / corr / O-rescale over the macro tile --
        float mx0 = -1e30f, mx1 = -1e30f;
#pragma unroll
        for (int sub = 0; sub < 2; sub++) {
            float (*S)[4] = Sall[sub];
#pragma unroll
            for (int nt = 0; nt < 8; nt++) {
                mx0 = fmaxf(mx0, fmaxf(S[nt][0], S[nt][1]));
                mx1 = fmaxf(mx1, fmaxf(S[nt][2], S[nt][3]));
            }
        }
        mx0 = fmaxf(mx0, __shfl_xor_sync(0xffffffffu, mx0, 1));
        mx0 = fmaxf(mx0, __shfl_xor_sync(0xffffffffu, mx0, 2));
        mx1 = fmaxf(mx1, __shfl_xor_sync(0xffffffffu, mx1, 1));
        mx1 = fmaxf(mx1, __shfl_xor_sync(0xffffffffu, mx1, 2));

        float mn0 = fmaxf(m0, mx0), mn1 = fmaxf(m1, mx1);
        float corr0 = exp2f((m0 - mn0) * L2E8);
        float corr1 = exp2f((m1 - mn1) * L2E8);
        m0 = mn0; m1 = mn1;
        const float c0 = mn0 * L2E8;
        const float c1 = mn1 * L2E8;

        {
            uint64_t cc0 = bcast2(corr0), cc1 = bcast2(corr1);
#pragma unroll
            for (int nt = 0; nt < 8; nt++) {
                mul2pair(O[nt][0], O[nt][1], cc0);
                mul2pair(O[nt][2], O[nt][3], cc1);
            }
        }
        l0 *= corr0;
        l1 *= corr1;

        // ---- Phase 2c+d: per-sub exp + fp16 pack + PV (2-pass fp16) -------
#pragma unroll
        for (int sub = 0; sub < 2; sub++) {
            const uint32_t soff = sub * 64 * AROW;
            const uint32_t sVs = sV + soff;
            float (*S)[4] = Sall[sub];

            float sum0 = 0.f, sum1 = 0.f;
#pragma unroll
            for (int nt = 0; nt < 8; nt++) {
                float p0 = exp2f(fmaf(S[nt][0], L2E8, -c0));
                float p1 = exp2f(fmaf(S[nt][1], L2E8, -c0));
                float p2 = exp2f(fmaf(S[nt][2], L2E8, -c1));
                float p3 = exp2f(fmaf(S[nt][3], L2E8, -c1));
                sum0 += p0 + p1; sum1 += p2 + p3;
                S[nt][0] = p0; S[nt][1] = p1; S[nt][2] = p2; S[nt][3] = p3;
            }
            l0 += sum0;
            l1 += sum1;

#pragma unroll
            for (int kk = 0; kk < 4; kk++) {
                uint32_t ah0, ah1, ah2, ah3, al0, al1, al2, al3;
                pack_f16_hilo(S[2*kk][0],   S[2*kk][1],   ah0, al0);
                pack_f16_hilo(S[2*kk][2],   S[2*kk][3],   ah1, al1);
                pack_f16_hilo(S[2*kk+1][0], S[2*kk+1][1], ah2, al2);
                pack_f16_hilo(S[2*kk+1][2], S[2*kk+1][3], ah3, al3);
#pragma unroll
                for (int npp = 0; npp < 2; npp++) {
                    uint32_t vb[2][4];
#pragma unroll
                    for (int q = 0; q < 2; q++) {
                        uint32_t addr = (kk*16 + v_rowsel)*AROW + (npp*2 + q)*32 + v_colsel;
                        ldm4t(vb[q][0], vb[q][1], vb[q][2], vb[q][3], sVs + addr);
                    }
                    float (*O4)[4] = &O[npp*4];
                    // pass hi (distance-4 over O4)
                    mma_f16(O4[0], ah0, ah1, ah2, ah3, vb[0][0], vb[0][1]);
                    mma_f16(O4[1], ah0, ah1, ah2, ah3, vb[0][2], vb[0][3]);
                    mma_f16(O4[2], ah0, ah1, ah2, ah3, vb[1][0], vb[1][1]);
                    mma_f16(O4[3], ah0, ah1, ah2, ah3, vb[1][2], vb[1][3]);
                    // pass lo
                    mma_f16(O4[0], al0, al1, al2, al3, vb[0][0], vb[0][1]);
                    mma_f16(O4[1], al0, al1, al2, al3, vb[0][2], vb[0][3]);
                    mma_f16(O4[2], al0, al1, al2, al3, vb[1][0], vb[1][1]);
                    mma_f16(O4[3], al0, al1, al2, al3, vb[1][2], vb[1][3]);
                }
            }
        }
        __syncthreads();
    }

    // final quad reduction of partial l, then normalize + store
    l0 += __shfl_xor_sync(0xffffffffu, l0, 1);
    l0 += __shfl_xor_sync(0xffffffffu, l0, 2);
    l1 += __shfl_xor_sync(0xffffffffu, l1, 1);
    l1 += __shfl_xor_sync(0xffffffffu, l1, 2);

    float inv0 = 1.f / l0, inv1 = 1.f / l1;
    size_t r0 = (size_t)(b_*NT + i0) * NC + h*HD + qr*2;
    size_t r1 = (size_t)(b_*NT + i1) * NC + h*HD + qr*2;
#pragma unroll
    for (int nt = 0; nt < 8; nt++) {
        split_store2(O[nt][0]*inv0, O[nt][1]*inv0, atth + r0 + nt*8, attl + r0 + nt*8);
        split_store2(O[nt][2]*inv1, O[nt][3]*inv1, atth + r1 + nt*8, attl + r1 + nt*8);
    }
}

// ---------------------------------------------------------------------------

extern "C" void kernel_launch(void* const* d_in, const int* in_sizes, int n_in,
                              void* d_out, int out_size)
{
    const float* x      = (const float*)d_in[0];
    const float* W_attn = (const float*)d_in[1];
    const float* W_proj = (const float*)d_in[2];
    const float* b_proj = (const float*)d_in[3];
    float* out = (float*)d_out;

    __nv_bfloat16 *xh, *xl, *wah, *wal, *wph, *wpl, *qkvh, *qkvl, *atth, *attl;
    __half *v16;
    cudaGetSymbolAddress((void**)&xh,   g_xh);
    cudaGetSymbolAddress((void**)&xl,   g_xl);
    cudaGetSymbolAddress((void**)&wah,  g_wah);
    cudaGetSymbolAddress((void**)&wal,  g_wal);
    cudaGetSymbolAddress((void**)&wph,  g_wph);
    cudaGetSymbolAddress((void**)&wpl,  g_wpl);
    cudaGetSymbolAddress((void**)&qkvh, g_qkvh);
    cudaGetSymbolAddress((void**)&qkvl, g_qkvl);
    cudaGetSymbolAddress((void**)&v16,  g_v16);
    cudaGetSymbolAddress((void**)&atth, g_atth);
    cudaGetSymbolAddress((void**)&attl, g_attl);

    constexpr int SM192 = 2*(2*GABUF + 2*192*GROW);   // 184320
    constexpr int SM256 = 2*(2*GABUF + 2*256*GROW);   // 221184

    cudaFuncSetAttribute(gemm_mma_kernel<192>,
                         cudaFuncAttributeMaxDynamicSharedMemorySize, SM192);
    cudaFuncSetAttribute(gemm_mma_kernel<256>,
                         cudaFuncAttributeMaxDynamicSharedMemorySize, SM256);
    cudaFuncSetAttribute(attn_fa2_kernel,
                         cudaFuncAttributeMaxDynamicSharedMemorySize, ATT_SMEM);

    split_all_kernel<<<(N4_X + N4_WA + N4_WP + 255) / 256, 256>>>(
        (const float4*)x, xh, xl,
        (const float4*)W_attn, wah, wal,
        (const float4*)W_proj, wph, wpl);

    // QKV: BN=192; Q/K as bf16 hi/lo, V routed to fp16 buffer
    gemm_mma_kernel<192><<<dim3(16, 64), 256, SM192>>>(
        xh, xl, wah, wal, qkvh, qkvl, v16, nullptr, nullptr, 3072, 0);

    // attention: QK bf16 3-pass, PV fp16 2-pass
    attn_fa2_kernel<<<dim3(16, 64), 256, ATT_SMEM>>>(qkvh, qkvl, v16, atth, attl);

    // proj: BN=256 + bias -> f32 out
    gemm_mma_kernel<256><<<dim3(4, 64), 256, SM256>>>(
        atth, attl, wph, wpl, nullptr, nullptr, nullptr, out, b_proj, 1024, 1);
}